// round 9
// baseline (speedup 1.0000x reference)
#include <cuda_runtime.h>
#include <cuda_fp16.h>
#include <math.h>
#include <stdint.h>

#define B_   8
#define N_   8192
#define C_   384
#define M_   65536
#define QKVC 1152

typedef unsigned long long u64;
typedef unsigned int u32;

// Scratch (static device arrays)
__device__ __half g_qkvTh[9216L * N_];        // fp16 [which(3)][b][h][d][n]
__device__ float g_rn[6144];
__device__ float g_nsq[6144L * 128];          // norm^2 partials [row][ntile64]
__device__ float g_Spart[8 * 64 * 2304];
__device__ float g_attnT[64 * 2304];
__device__ __half g_xh[(size_t)M_ * C_];      // A of GEMM1: fp16(x)
__device__ __half g_yh[(size_t)M_ * C_];      // A of GEMM2: fp16(y)
__device__ __half g_wqhi[QKVC * C_], g_wqlo[QKVC * C_];
__device__ __half g_wphi[C_ * C_], g_wplo[C_ * C_];

// ---- helpers ----------------------------------------------------------------
__device__ __forceinline__ u64 pk2(float a, float b) {
    u64 r; asm("mov.b64 %0, {%1,%2};" : "=l"(r) : "f"(a), "f"(b)); return r;
}
__device__ __forceinline__ float2 upk(u64 v) {
    float2 r; asm("mov.b64 {%0,%1}, %2;" : "=f"(r.x), "=f"(r.y) : "l"(v)); return r;
}
#define FMA2(acc, a, b) asm("fma.rn.f32x2 %0, %1, %2, %0;" : "+l"(acc) : "l"(a), "l"(b))

__device__ __forceinline__ u32 s2u(const void* p) {
    u32 a;
    asm("{ .reg .u64 t; cvta.to.shared.u64 t, %1; cvt.u32.u64 %0, t; }" : "=r"(a) : "l"(p));
    return a;
}
__device__ __forceinline__ void cp16(u32 dst, const void* src) {
    asm volatile("cp.async.cg.shared.global [%0], [%1], 16;" :: "r"(dst), "l"(src));
}
__device__ __forceinline__ void ldsm4(u32* r, u32 addr) {
    asm volatile("ldmatrix.sync.aligned.m8n8.x4.shared.b16 {%0,%1,%2,%3}, [%4];"
        : "=r"(r[0]), "=r"(r[1]), "=r"(r[2]), "=r"(r[3]) : "r"(addr));
}
__device__ __forceinline__ void mma_f16(float* d, const u32* a, u32 b0, u32 b1) {
    asm volatile("mma.sync.aligned.m16n8k16.row.col.f32.f16.f16.f32 "
        "{%0,%1,%2,%3}, {%4,%5,%6,%7}, {%8,%9}, {%0,%1,%2,%3};"
        : "+f"(d[0]), "+f"(d[1]), "+f"(d[2]), "+f"(d[3])
        : "r"(a[0]), "r"(a[1]), "r"(a[2]), "r"(a[3]), "r"(b0), "r"(b1));
}
__device__ __forceinline__ u32 packh2(__half a, __half b) {
    return (u32)*(unsigned short*)&a | ((u32)*(unsigned short*)&b << 16);
}
__device__ __forceinline__ void split2h(float a, float b, u32& hi, u32& lo) {
    __half ha = __float2half_rn(a), hb = __float2half_rn(b);
    __half la = __float2half_rn(a - __half2float(ha));
    __half lb = __float2half_rn(b - __half2float(hb));
    hi = packh2(ha, hb);
    lo = packh2(la, lb);
}
__device__ __forceinline__ u32 cvt2h(float a, float b) {
    return packh2(__float2half_rn(a), __float2half_rn(b));
}

// ---------------------------------------------------------------------------
// Pre-convert: SEL 0 = x -> fp16 (hi only); SEL 1 = w_qkv, 2 = w_proj -> hi/lo
// ---------------------------------------------------------------------------
template<int SEL>
__global__ void k_split(const float* __restrict__ src, int n4)
{
    int i = blockIdx.x * 256 + threadIdx.x;
    if (i >= n4) return;
    float4 v = ((const float4*)src)[i];
    if (SEL == 0) {
        ((uint2*)g_xh)[i] = make_uint2(cvt2h(v.x, v.y), cvt2h(v.z, v.w));
    } else {
        __half* hi = (SEL == 1) ? g_wqhi : g_wphi;
        __half* lo = (SEL == 1) ? g_wqlo : g_wplo;
        u32 h0, l0, h1, l1;
        split2h(v.x, v.y, h0, l0);
        split2h(v.z, v.w, h1, l1);
        ((uint2*)hi)[i] = make_uint2(h0, h1);
        ((uint2*)lo)[i] = make_uint2(l0, l1);
    }
}

// ---------------------------------------------------------------------------
// Tensor-core GEMM: C = A(m,k) * B(n,k)^T, K=384, A fp16, B fp16 hi/lo
// 256 threads, 8 warps (2m x 4n), 64x32 warp tiles; 3-stage cp.async, BK=16.
// __launch_bounds__(256, 2): 2 CTAs co-resident per SM.
// MODE 0: A = fp16(x), B = w_qkv -> fp16 scatter into g_qkvTh + norm^2 partials
// MODE 1: A = fp16(y), B = w_proj -> +bias, row-major fp32 out
// ---------------------------------------------------------------------------
#define STAGE_B   12288
#define GEMM_SMEM 36864   // 3 stages * 12KB; epilogue T uses 34816

template<int MODE>
__global__ void __launch_bounds__(256, 2)
k_gemm(const float* __restrict__ bias, float* __restrict__ outp)
{
    extern __shared__ char smem[];
    const u32 sb = s2u(smem);
    const int tid  = threadIdx.x;
    const int lane = tid & 31, wid = tid >> 5;
    const int wm = wid & 1, wn = wid >> 1;          // warp grid 2m x 4n
    const int row0 = blockIdx.y * 128;
    const int col0 = blockIdx.x * 128;

    const __half* Ah  = (MODE == 0) ? g_xh   : g_yh;
    const __half* Bhi = (MODE == 0) ? g_wqhi : g_wphi;
    const __half* Blo = (MODE == 0) ? g_wqlo : g_wplo;

    float acc[4][4][4];
#pragma unroll
    for (int a = 0; a < 4; a++)
#pragma unroll
        for (int b = 0; b < 4; b++)
#pragma unroll
            for (int c = 0; c < 4; c++) acc[a][b][c] = 0.f;

    // cp.async: stage = [A | Bhi | Blo], each 128 rows x 16 fp16 (32B/row)
    const int crow = tid >> 1;
    const int cch  = tid & 1;
    const int cphys = cch ^ ((crow >> 2) & 1);
    const u32 cso = crow * 32 + cphys * 16;
    const size_t gra = (size_t)(row0 + crow) * C_ + cch * 8;
    const size_t grb = (size_t)(col0 + crow) * C_ + cch * 8;

    auto load_tile = [&](int it, int s) {
        const u32 st = sb + s * STAGE_B;
        const int k0 = it * 16;
        cp16(st +    0 + cso, Ah  + gra + k0);
        cp16(st + 4096 + cso, Bhi + grb + k0);
        cp16(st + 8192 + cso, Blo + grb + k0);
    };

    // ldmatrix.x4 address for 16-row group starting at r (row stride 32B)
    const int fr_off = (lane & 7) + ((lane >> 3) & 1) * 8;
    const int fr_ch  = lane >> 4;
    auto frag_addr = [&](u32 base, int r) -> u32 {
        int row = r + fr_off;
        int phys = fr_ch ^ ((row >> 2) & 1);
        return base + row * 32 + phys * 16;
    };

    auto compute = [&](int s) {
        const u32 st = sb + s * STAGE_B;
        u32 ah[4][4], bh[2][4], bl[2][4];
#pragma unroll
        for (int mt = 0; mt < 4; mt++)
            ldsm4(ah[mt], frag_addr(st + 0, wm * 64 + mt * 16));
#pragma unroll
        for (int np = 0; np < 2; np++)
            ldsm4(bh[np], frag_addr(st + 4096, wn * 32 + np * 16));
        // term 0: A * Bhi (16 independent accumulators)
#pragma unroll
        for (int mt = 0; mt < 4; mt++)
#pragma unroll
            for (int np = 0; np < 2; np++)
#pragma unroll
                for (int sub = 0; sub < 2; sub++)
                    mma_f16(acc[mt][np * 2 + sub], ah[mt], bh[np][sub], bh[np][sub + 2]);
#pragma unroll
        for (int np = 0; np < 2; np++)
            ldsm4(bl[np], frag_addr(st + 8192, wn * 32 + np * 16));
        // term 1: A * Blo
#pragma unroll
        for (int mt = 0; mt < 4; mt++)
#pragma unroll
            for (int np = 0; np < 2; np++)
#pragma unroll
                for (int sub = 0; sub < 2; sub++)
                    mma_f16(acc[mt][np * 2 + sub], ah[mt], bl[np][sub], bl[np][sub + 2]);
    };

    load_tile(0, 0);
    asm volatile("cp.async.commit_group;" ::: "memory");
    load_tile(1, 1);
    asm volatile("cp.async.commit_group;" ::: "memory");

#pragma unroll 1
    for (int it = 0; it < 24; it++) {
        if (it < 23) {
            asm volatile("cp.async.wait_group 1;" ::: "memory");
        } else {
            asm volatile("cp.async.wait_group 0;" ::: "memory");
        }
        __syncthreads();
        if (it + 2 < 24) {
            load_tile(it + 2, (it + 2) % 3);
            asm volatile("cp.async.commit_group;" ::: "memory");
        }
        compute(it % 3);
    }

    // Epilogue: stage halves through smem T[128][68] for coalesced stores
    float* T = (float*)smem;
    const int g = lane >> 2, tq = lane & 3;
    const int which = col0 / C_;

#pragma unroll 1
    for (int jh = 0; jh < 2; jh++) {
        __syncthreads();
        if (MODE == 0) {
            if (wm == jh) {
#pragma unroll
                for (int mt = 0; mt < 4; mt++)
#pragma unroll
                    for (int nt = 0; nt < 4; nt++) {
                        int ml = mt * 16 + g;
                        int nl = wn * 32 + nt * 8 + tq * 2;
#pragma unroll
                        for (int rr = 0; rr < 4; rr++)
                            T[(nl + (rr & 1)) * 68 + ml + (rr >> 1) * 8] = acc[mt][nt][rr];
                    }
            }
        } else {
            if ((wn >> 1) == jh) {
#pragma unroll
                for (int mt = 0; mt < 4; mt++)
#pragma unroll
                    for (int nt = 0; nt < 4; nt++) {
                        int ml = wm * 64 + mt * 16 + g;
                        int nl = (wn & 1) * 32 + nt * 8 + tq * 2;
#pragma unroll
                        for (int rr = 0; rr < 4; rr++)
                            T[(ml + (rr >> 1) * 8) * 68 + nl + (rr & 1)] = acc[mt][nt][rr];
                    }
            }
        }
        __syncthreads();
        if (MODE == 0) {
            const int bb = row0 >> 13;
            const int n0 = (row0 & (N_ - 1)) + jh * 64;
            const int ccb = col0 - which * C_;
            const int ntile = n0 >> 6;               // 0..127 (64-n granules)
#pragma unroll
            for (int t = 0; t < 8; t++) {
                int fid = tid + t * 256;
                int i = fid >> 4;                  // channel-local 0..127
                int j = (fid & 15) * 4;            // n offset 0..60
                float4 v = *(float4*)&T[i * 68 + j];
                // fp16 store (q,k,v all half precision downstream)
                __half hx = __float2half_rn(v.x), hy = __float2half_rn(v.y);
                __half hz = __float2half_rn(v.z), hw = __float2half_rn(v.w);
                int row = which * 3072 + bb * C_ + ccb + i;
                *(uint2*)(g_qkvTh + (size_t)row * N_ + n0 + j) =
                    make_uint2(packh2(hx, hy), packh2(hz, hw));
                if (which < 2) {
                    // norms of the ROUNDED values -> normalization exact for stored q,k
                    float rx = __half2float(hx), ry = __half2float(hy);
                    float rz = __half2float(hz), rw = __half2float(hw);
                    float sq = rx * rx + ry * ry + rz * rz + rw * rw;
                    sq += __shfl_xor_sync(0xffffffffu, sq, 1);
                    sq += __shfl_xor_sync(0xffffffffu, sq, 2);
                    sq += __shfl_xor_sync(0xffffffffu, sq, 4);
                    sq += __shfl_xor_sync(0xffffffffu, sq, 8);
                    if ((tid & 15) == 0)
                        g_nsq[(size_t)row * 128 + ntile] = sq;
                }
            }
        } else {
            const int c0 = col0 + jh * 64;
#pragma unroll
            for (int t = 0; t < 8; t++) {
                int fid = tid + t * 256;
                int i = fid >> 4;
                int j = (fid & 15) * 4;
                float4 v = *(float4*)&T[i * 68 + j];
                float4 bv = *(const float4*)(bias + c0 + j);
                v.x += bv.x; v.y += bv.y; v.z += bv.z; v.w += bv.w;
                *(float4*)(outp + (size_t)(row0 + i) * C_ + c0 + j) = v;
            }
        }
    }
}

// ---------------------------------------------------------------------------
// K2a: reduce norm^2 partials -> 1/max(norm,eps)
// ---------------------------------------------------------------------------
__global__ void k_nred()
{
    const int row = blockIdx.x;           // 0..6143
    const int t = threadIdx.x;            // 32 threads
    const float* p = g_nsq + (size_t)row * 128;
    float s = p[t] + p[t + 32] + p[t + 64] + p[t + 96];
#pragma unroll
    for (int o = 16; o > 0; o >>= 1)
        s += __shfl_xor_sync(0xffffffffu, s, o);
    if (t == 0)
        g_rn[row] = 1.0f / fmaxf(sqrtf(s), 1e-12f);
}

// ---------------------------------------------------------------------------
// K2b: Gram partials (q,k read as fp16, accumulated fp32)
// ---------------------------------------------------------------------------
__global__ void k_logits()
{
    const int chunk = blockIdx.x;
    const int bh    = blockIdx.y;
    const int tid   = threadIdx.x;
    __shared__ float Qs[32][49];
    __shared__ float Ks[32][49];

    const int td = (tid >> 4) * 3;
    const int te = (tid & 15) * 3;
    float acc[3][3] = {};

    const size_t qbase = (size_t)(bh * 48) * N_ + (size_t)chunk * 1024;
    const size_t kbase = qbase + (size_t)3072 * N_;

    for (int t = 0; t < 1024; t += 32) {
#pragma unroll
        for (int it = 0; it < 3; it++) {
            int id  = tid + it * 256;
            int isK = (id >= 384);
            int lidx = id - isK * 384;
            int d = lidx >> 3;
            int nseg = (lidx & 7) * 4;
            size_t base = isK ? kbase : qbase;
            uint2 raw = *(const uint2*)(g_qkvTh + base + (size_t)d * N_ + t + nseg);
            float2 f01 = __half22float2(*(__half2*)&raw.x);
            float2 f23 = __half22float2(*(__half2*)&raw.y);
            float (*S)[49] = isK ? Ks : Qs;
            S[nseg + 0][d] = f01.x; S[nseg + 1][d] = f01.y;
            S[nseg + 2][d] = f23.x; S[nseg + 3][d] = f23.y;
        }
        __syncthreads();
#pragma unroll
        for (int kk = 0; kk < 32; kk++) {
            float q0 = Qs[kk][td], q1 = Qs[kk][td + 1], q2 = Qs[kk][td + 2];
            float p0 = Ks[kk][te], p1 = Ks[kk][te + 1], p2 = Ks[kk][te + 2];
            acc[0][0] += q0 * p0; acc[0][1] += q0 * p1; acc[0][2] += q0 * p2;
            acc[1][0] += q1 * p0; acc[1][1] += q1 * p1; acc[1][2] += q1 * p2;
            acc[2][0] += q2 * p0; acc[2][1] += q2 * p1; acc[2][2] += q2 * p2;
        }
        __syncthreads();
    }

    float* outp = g_Spart + ((size_t)chunk * 64 + bh) * 2304;
#pragma unroll
    for (int i = 0; i < 3; i++)
#pragma unroll
        for (int j = 0; j < 3; j++)
            outp[(td + i) * 48 + (te + j)] = acc[i][j];
}

// ---------------------------------------------------------------------------
// K2c: softmax
// ---------------------------------------------------------------------------
__global__ void k_softmax()
{
    const int bh = blockIdx.x;
    const int d  = threadIdx.x;
    if (d >= 48) return;
    const float rq = g_rn[bh * 48 + d];
    const float* rk = g_rn + 3072 + bh * 48;

    float vals[48];
    float mx = -1e30f;
#pragma unroll
    for (int e = 0; e < 48; e++) {
        float s = 0.f;
#pragma unroll
        for (int c = 0; c < 8; c++)
            s += g_Spart[((size_t)c * 64 + bh) * 2304 + d * 48 + e];
        float v = s * rq * rk[e];
        vals[e] = v;
        mx = fmaxf(mx, v);
    }
    float sum = 0.f;
#pragma unroll
    for (int e = 0; e < 48; e++) {
        vals[e] = expf(vals[e] - mx);
        sum += vals[e];
    }
    float inv = 1.0f / sum;
#pragma unroll
    for (int e = 0; e < 48; e++)
        g_attnT[(size_t)bh * 2304 + e * 48 + d] = vals[e] * inv;
}

// ---------------------------------------------------------------------------
// K2d: y = attn @ v (v read fp16), emitted as fp16, row-major [m][j] for K3
// ---------------------------------------------------------------------------
__global__ void k_av()
{
    const int chunk = blockIdx.x;     // 0..31 (256 n each)
    const int bh    = blockIdx.y;
    const int tid   = threadIdx.x;
    __shared__ __align__(16) float At[2304];   // At[e*48 + d]
#pragma unroll
    for (int i = 0; i < 9; i++)
        At[tid + i * 256] = g_attnT[(size_t)bh * 2304 + tid + i * 256];
    __syncthreads();

    const int n = chunk * 256 + tid;
    const size_t vbase = ((size_t)(2 * 3072 + bh * 48)) * N_ + n;
    u64 acc2[24];
#pragma unroll
    for (int i = 0; i < 24; i++) acc2[i] = 0ULL;

#pragma unroll 4
    for (int e = 0; e < 48; e++) {
        float vv = __half2float(g_qkvTh[vbase + (size_t)e * N_]);
        u64 vp = pk2(vv, vv);
        const ulonglong2* arow = (const ulonglong2*)&At[e * 48];
#pragma unroll
        for (int t = 0; t < 12; t++) {
            ulonglong2 a2 = arow[t];
            FMA2(acc2[2 * t + 0], a2.x, vp);
            FMA2(acc2[2 * t + 1], a2.y, vp);
        }
    }
    const int b = bh >> 3, h = bh & 7;
    const size_t base = ((size_t)(b * N_ + n)) * C_ + h * 48;
    u32* yh = (u32*)(g_yh + base);
#pragma unroll
    for (int t = 0; t < 12; t++) {
        float2 f0 = upk(acc2[2 * t + 0]);
        float2 f1 = upk(acc2[2 * t + 1]);
        yh[2 * t + 0] = cvt2h(f0.x, f0.y);
        yh[2 * t + 1] = cvt2h(f1.x, f1.y);
    }
}

// ---------------------------------------------------------------------------
extern "C" void kernel_launch(void* const* d_in, const int* in_sizes, int n_in,
                              void* d_out, int out_size)
{
    const float* x      = (const float*)d_in[0];
    const float* w_qkv  = (const float*)d_in[1];
    const float* w_proj = (const float*)d_in[2];
    const float* b_proj = (const float*)d_in[3];
    float* out = (float*)d_out;

    const int n4x = M_ * C_ / 4;
    const int n4q = QKVC * C_ / 4;
    const int n4p = C_ * C_ / 4;
    k_split<0><<<(n4x + 255) / 256, 256>>>(x, n4x);
    k_split<1><<<(n4q + 255) / 256, 256>>>(w_qkv, n4q);
    k_split<2><<<(n4p + 255) / 256, 256>>>(w_proj, n4p);

    dim3 g1(QKVC / 128, M_ / 128);        // 9 x 512
    k_gemm<0><<<g1, 256, GEMM_SMEM>>>(nullptr, nullptr);

    k_nred<<<6144, 32>>>();

    dim3 g2(8, 64);
    k_logits<<<g2, 256>>>();

    k_softmax<<<64, 48>>>();

    dim3 g3(32, 64);
    k_av<<<g3, 256>>>();

    dim3 g4(C_ / 128, M_ / 128);          // 3 x 512
    k_gemm<1><<<g4, 256, GEMM_SMEM>>>(b_proj, out);
}

// round 10
// speedup vs baseline: 1.2603x; 1.2603x over previous
#include <cuda_runtime.h>
#include <cuda_fp16.h>
#include <math.h>
#include <stdint.h>

#define B_   8
#define N_   8192
#define C_   384
#define M_   65536
#define QKVC 1152

typedef unsigned long long u64;
typedef unsigned int u32;

// Scratch (static device arrays)
__device__ __half g_qkvTh[9216L * N_];        // fp16 [which(3)][b][h][d][n]
__device__ float g_rn[6144];
__device__ float g_nsq[6144L * 128];          // norm^2 partials [row][ntile64]
__device__ float g_Spart[8 * 64 * 2304];
__device__ float g_attnT[64 * 2304];
__device__ __half g_xh[(size_t)M_ * C_];      // A of GEMM1: fp16(x)
__device__ __half g_yh[(size_t)M_ * C_];      // A of GEMM2: fp16(y)
__device__ __half g_wqh[QKVC * C_];           // fp16(w_qkv)
__device__ __half g_wph[C_ * C_];             // fp16(w_proj)

// ---- helpers ----------------------------------------------------------------
__device__ __forceinline__ u64 pk2(float a, float b) {
    u64 r; asm("mov.b64 %0, {%1,%2};" : "=l"(r) : "f"(a), "f"(b)); return r;
}
__device__ __forceinline__ float2 upk(u64 v) {
    float2 r; asm("mov.b64 {%0,%1}, %2;" : "=f"(r.x), "=f"(r.y) : "l"(v)); return r;
}
#define FMA2(acc, a, b) asm("fma.rn.f32x2 %0, %1, %2, %0;" : "+l"(acc) : "l"(a), "l"(b))

__device__ __forceinline__ u32 s2u(const void* p) {
    u32 a;
    asm("{ .reg .u64 t; cvta.to.shared.u64 t, %1; cvt.u32.u64 %0, t; }" : "=r"(a) : "l"(p));
    return a;
}
__device__ __forceinline__ void cp16(u32 dst, const void* src) {
    asm volatile("cp.async.cg.shared.global [%0], [%1], 16;" :: "r"(dst), "l"(src));
}
__device__ __forceinline__ void ldsm4(u32* r, u32 addr) {
    asm volatile("ldmatrix.sync.aligned.m8n8.x4.shared.b16 {%0,%1,%2,%3}, [%4];"
        : "=r"(r[0]), "=r"(r[1]), "=r"(r[2]), "=r"(r[3]) : "r"(addr));
}
__device__ __forceinline__ void mma_f16(float* d, const u32* a, u32 b0, u32 b1) {
    asm volatile("mma.sync.aligned.m16n8k16.row.col.f32.f16.f16.f32 "
        "{%0,%1,%2,%3}, {%4,%5,%6,%7}, {%8,%9}, {%0,%1,%2,%3};"
        : "+f"(d[0]), "+f"(d[1]), "+f"(d[2]), "+f"(d[3])
        : "r"(a[0]), "r"(a[1]), "r"(a[2]), "r"(a[3]), "r"(b0), "r"(b1));
}
__device__ __forceinline__ u32 packh2(__half a, __half b) {
    return (u32)*(unsigned short*)&a | ((u32)*(unsigned short*)&b << 16);
}
__device__ __forceinline__ u32 cvt2h(float a, float b) {
    return packh2(__float2half_rn(a), __float2half_rn(b));
}

// ---------------------------------------------------------------------------
// Pre-convert fp32 -> fp16   (SEL: 0=x, 1=w_qkv, 2=w_proj)
// ---------------------------------------------------------------------------
template<int SEL>
__global__ void k_split(const float* __restrict__ src, int n4)
{
    __half* dst = (SEL == 0) ? g_xh : (SEL == 1) ? g_wqh : g_wph;
    int i = blockIdx.x * 256 + threadIdx.x;
    if (i >= n4) return;
    float4 v = ((const float4*)src)[i];
    ((uint2*)dst)[i] = make_uint2(cvt2h(v.x, v.y), cvt2h(v.z, v.w));
}

// ---------------------------------------------------------------------------
// Tensor-core GEMM: C = A(m,k) * B(n,k)^T, K=384, plain fp16, fp32 accum
// 256 threads, 8 warps (2m x 4n), 64x32 warp tiles; 3-stage cp.async, BK=16.
// __launch_bounds__(256, 2): 2 CTAs co-resident per SM.
// MODE 0: A = fp16(x), B = fp16(w_qkv) -> fp16 scatter into g_qkvTh + norm^2
// MODE 1: A = fp16(y), B = fp16(w_proj) -> +bias, row-major fp32 out
// ---------------------------------------------------------------------------
#define STAGE_B   8192
#define GEMM_SMEM 34816   // epilogue T (128*68*4); mainloop uses 3*8KB = 24KB

template<int MODE>
__global__ void __launch_bounds__(256, 2)
k_gemm(const float* __restrict__ bias, float* __restrict__ outp)
{
    extern __shared__ char smem[];
    const u32 sb = s2u(smem);
    const int tid  = threadIdx.x;
    const int lane = tid & 31, wid = tid >> 5;
    const int wm = wid & 1, wn = wid >> 1;          // warp grid 2m x 4n
    const int row0 = blockIdx.y * 128;
    const int col0 = blockIdx.x * 128;

    const __half* Ah = (MODE == 0) ? g_xh  : g_yh;
    const __half* Bh = (MODE == 0) ? g_wqh : g_wph;

    float acc[4][4][4];
#pragma unroll
    for (int a = 0; a < 4; a++)
#pragma unroll
        for (int b = 0; b < 4; b++)
#pragma unroll
            for (int c = 0; c < 4; c++) acc[a][b][c] = 0.f;

    // cp.async: stage = [A | B], each 128 rows x 16 fp16 (32B/row)
    const int crow = tid >> 1;
    const int cch  = tid & 1;
    const int cphys = cch ^ ((crow >> 2) & 1);
    const u32 cso = crow * 32 + cphys * 16;
    const size_t gra = (size_t)(row0 + crow) * C_ + cch * 8;
    const size_t grb = (size_t)(col0 + crow) * C_ + cch * 8;

    auto load_tile = [&](int it, int s) {
        const u32 st = sb + s * STAGE_B;
        const int k0 = it * 16;
        cp16(st +    0 + cso, Ah + gra + k0);
        cp16(st + 4096 + cso, Bh + grb + k0);
    };

    // ldmatrix.x4 address for 16-row group starting at r (row stride 32B)
    const int fr_off = (lane & 7) + ((lane >> 3) & 1) * 8;
    const int fr_ch  = lane >> 4;
    auto frag_addr = [&](u32 base, int r) -> u32 {
        int row = r + fr_off;
        int phys = fr_ch ^ ((row >> 2) & 1);
        return base + row * 32 + phys * 16;
    };

    auto compute = [&](int s) {
        const u32 st = sb + s * STAGE_B;
        u32 ah[4][4], bh[2][4];
#pragma unroll
        for (int mt = 0; mt < 4; mt++)
            ldsm4(ah[mt], frag_addr(st + 0, wm * 64 + mt * 16));
#pragma unroll
        for (int np = 0; np < 2; np++)
            ldsm4(bh[np], frag_addr(st + 4096, wn * 32 + np * 16));
#pragma unroll
        for (int mt = 0; mt < 4; mt++)
#pragma unroll
            for (int np = 0; np < 2; np++)
#pragma unroll
                for (int sub = 0; sub < 2; sub++)
                    mma_f16(acc[mt][np * 2 + sub], ah[mt], bh[np][sub], bh[np][sub + 2]);
    };

    load_tile(0, 0);
    asm volatile("cp.async.commit_group;" ::: "memory");
    load_tile(1, 1);
    asm volatile("cp.async.commit_group;" ::: "memory");

#pragma unroll 1
    for (int it = 0; it < 24; it++) {
        if (it < 23) {
            asm volatile("cp.async.wait_group 1;" ::: "memory");
        } else {
            asm volatile("cp.async.wait_group 0;" ::: "memory");
        }
        __syncthreads();
        if (it + 2 < 24) {
            load_tile(it + 2, (it + 2) % 3);
            asm volatile("cp.async.commit_group;" ::: "memory");
        }
        compute(it % 3);
    }

    // Epilogue: stage halves through smem T[128][68] for coalesced stores
    float* T = (float*)smem;
    const int g = lane >> 2, tq = lane & 3;
    const int which = col0 / C_;

#pragma unroll 1
    for (int jh = 0; jh < 2; jh++) {
        __syncthreads();
        if (MODE == 0) {
            if (wm == jh) {
#pragma unroll
                for (int mt = 0; mt < 4; mt++)
#pragma unroll
                    for (int nt = 0; nt < 4; nt++) {
                        int ml = mt * 16 + g;
                        int nl = wn * 32 + nt * 8 + tq * 2;
#pragma unroll
                        for (int rr = 0; rr < 4; rr++)
                            T[(nl + (rr & 1)) * 68 + ml + (rr >> 1) * 8] = acc[mt][nt][rr];
                    }
            }
        } else {
            if ((wn >> 1) == jh) {
#pragma unroll
                for (int mt = 0; mt < 4; mt++)
#pragma unroll
                    for (int nt = 0; nt < 4; nt++) {
                        int ml = wm * 64 + mt * 16 + g;
                        int nl = (wn & 1) * 32 + nt * 8 + tq * 2;
#pragma unroll
                        for (int rr = 0; rr < 4; rr++)
                            T[(ml + (rr >> 1) * 8) * 68 + nl + (rr & 1)] = acc[mt][nt][rr];
                    }
            }
        }
        __syncthreads();
        if (MODE == 0) {
            const int bb = row0 >> 13;
            const int n0 = (row0 & (N_ - 1)) + jh * 64;
            const int ccb = col0 - which * C_;
            const int ntile = n0 >> 6;               // 0..127 (64-n granules)
#pragma unroll
            for (int t = 0; t < 8; t++) {
                int fid = tid + t * 256;
                int i = fid >> 4;                  // channel-local 0..127
                int j = (fid & 15) * 4;            // n offset 0..60
                float4 v = *(float4*)&T[i * 68 + j];
                __half hx = __float2half_rn(v.x), hy = __float2half_rn(v.y);
                __half hz = __float2half_rn(v.z), hw = __float2half_rn(v.w);
                int row = which * 3072 + bb * C_ + ccb + i;
                *(uint2*)(g_qkvTh + (size_t)row * N_ + n0 + j) =
                    make_uint2(packh2(hx, hy), packh2(hz, hw));
                if (which < 2) {
                    float rx = __half2float(hx), ry = __half2float(hy);
                    float rz = __half2float(hz), rw = __half2float(hw);
                    float sq = rx * rx + ry * ry + rz * rz + rw * rw;
                    sq += __shfl_xor_sync(0xffffffffu, sq, 1);
                    sq += __shfl_xor_sync(0xffffffffu, sq, 2);
                    sq += __shfl_xor_sync(0xffffffffu, sq, 4);
                    sq += __shfl_xor_sync(0xffffffffu, sq, 8);
                    if ((tid & 15) == 0)
                        g_nsq[(size_t)row * 128 + ntile] = sq;
                }
            }
        } else {
            const int c0 = col0 + jh * 64;
#pragma unroll
            for (int t = 0; t < 8; t++) {
                int fid = tid + t * 256;
                int i = fid >> 4;
                int j = (fid & 15) * 4;
                float4 v = *(float4*)&T[i * 68 + j];
                float4 bv = *(const float4*)(bias + c0 + j);
                v.x += bv.x; v.y += bv.y; v.z += bv.z; v.w += bv.w;
                *(float4*)(outp + (size_t)(row0 + i) * C_ + c0 + j) = v;
            }
        }
    }
}

// ---------------------------------------------------------------------------
// K2a: reduce norm^2 partials -> 1/max(norm,eps)
// ---------------------------------------------------------------------------
__global__ void k_nred()
{
    const int row = blockIdx.x;           // 0..6143
    const int t = threadIdx.x;            // 32 threads
    const float* p = g_nsq + (size_t)row * 128;
    float s = p[t] + p[t + 32] + p[t + 64] + p[t + 96];
#pragma unroll
    for (int o = 16; o > 0; o >>= 1)
        s += __shfl_xor_sync(0xffffffffu, s, o);
    if (t == 0)
        g_rn[row] = 1.0f / fmaxf(sqrtf(s), 1e-12f);
}

// ---------------------------------------------------------------------------
// K2b: Gram partials (q,k read as fp16, accumulated fp32)
// ---------------------------------------------------------------------------
__global__ void k_logits()
{
    const int chunk = blockIdx.x;
    const int bh    = blockIdx.y;
    const int tid   = threadIdx.x;
    __shared__ float Qs[32][49];
    __shared__ float Ks[32][49];

    const int td = (tid >> 4) * 3;
    const int te = (tid & 15) * 3;
    float acc[3][3] = {};

    const size_t qbase = (size_t)(bh * 48) * N_ + (size_t)chunk * 1024;
    const size_t kbase = qbase + (size_t)3072 * N_;

    for (int t = 0; t < 1024; t += 32) {
#pragma unroll
        for (int it = 0; it < 3; it++) {
            int id  = tid + it * 256;
            int isK = (id >= 384);
            int lidx = id - isK * 384;
            int d = lidx >> 3;
            int nseg = (lidx & 7) * 4;
            size_t base = isK ? kbase : qbase;
            uint2 raw = *(const uint2*)(g_qkvTh + base + (size_t)d * N_ + t + nseg);
            float2 f01 = __half22float2(*(__half2*)&raw.x);
            float2 f23 = __half22float2(*(__half2*)&raw.y);
            float (*S)[49] = isK ? Ks : Qs;
            S[nseg + 0][d] = f01.x; S[nseg + 1][d] = f01.y;
            S[nseg + 2][d] = f23.x; S[nseg + 3][d] = f23.y;
        }
        __syncthreads();
#pragma unroll
        for (int kk = 0; kk < 32; kk++) {
            float q0 = Qs[kk][td], q1 = Qs[kk][td + 1], q2 = Qs[kk][td + 2];
            float p0 = Ks[kk][te], p1 = Ks[kk][te + 1], p2 = Ks[kk][te + 2];
            acc[0][0] += q0 * p0; acc[0][1] += q0 * p1; acc[0][2] += q0 * p2;
            acc[1][0] += q1 * p0; acc[1][1] += q1 * p1; acc[1][2] += q1 * p2;
            acc[2][0] += q2 * p0; acc[2][1] += q2 * p1; acc[2][2] += q2 * p2;
        }
        __syncthreads();
    }

    float* outp = g_Spart + ((size_t)chunk * 64 + bh) * 2304;
#pragma unroll
    for (int i = 0; i < 3; i++)
#pragma unroll
        for (int j = 0; j < 3; j++)
            outp[(td + i) * 48 + (te + j)] = acc[i][j];
}

// ---------------------------------------------------------------------------
// K2c: softmax
// ---------------------------------------------------------------------------
__global__ void k_softmax()
{
    const int bh = blockIdx.x;
    const int d  = threadIdx.x;
    if (d >= 48) return;
    const float rq = g_rn[bh * 48 + d];
    const float* rk = g_rn + 3072 + bh * 48;

    float vals[48];
    float mx = -1e30f;
#pragma unroll
    for (int e = 0; e < 48; e++) {
        float s = 0.f;
#pragma unroll
        for (int c = 0; c < 8; c++)
            s += g_Spart[((size_t)c * 64 + bh) * 2304 + d * 48 + e];
        float v = s * rq * rk[e];
        vals[e] = v;
        mx = fmaxf(mx, v);
    }
    float sum = 0.f;
#pragma unroll
    for (int e = 0; e < 48; e++) {
        vals[e] = expf(vals[e] - mx);
        sum += vals[e];
    }
    float inv = 1.0f / sum;
#pragma unroll
    for (int e = 0; e < 48; e++)
        g_attnT[(size_t)bh * 2304 + e * 48 + d] = vals[e] * inv;
}

// ---------------------------------------------------------------------------
// K2d: y = attn @ v (v read fp16), emitted as fp16, row-major [m][j] for K3
// ---------------------------------------------------------------------------
__global__ void k_av()
{
    const int chunk = blockIdx.x;     // 0..31 (256 n each)
    const int bh    = blockIdx.y;
    const int tid   = threadIdx.x;
    __shared__ __align__(16) float At[2304];   // At[e*48 + d]
#pragma unroll
    for (int i = 0; i < 9; i++)
        At[tid + i * 256] = g_attnT[(size_t)bh * 2304 + tid + i * 256];
    __syncthreads();

    const int n = chunk * 256 + tid;
    const size_t vbase = ((size_t)(2 * 3072 + bh * 48)) * N_ + n;
    u64 acc2[24];
#pragma unroll
    for (int i = 0; i < 24; i++) acc2[i] = 0ULL;

#pragma unroll 4
    for (int e = 0; e < 48; e++) {
        float vv = __half2float(g_qkvTh[vbase + (size_t)e * N_]);
        u64 vp = pk2(vv, vv);
        const ulonglong2* arow = (const ulonglong2*)&At[e * 48];
#pragma unroll
        for (int t = 0; t < 12; t++) {
            ulonglong2 a2 = arow[t];
            FMA2(acc2[2 * t + 0], a2.x, vp);
            FMA2(acc2[2 * t + 1], a2.y, vp);
        }
    }
    const int b = bh >> 3, h = bh & 7;
    const size_t base = ((size_t)(b * N_ + n)) * C_ + h * 48;
    u32* yh = (u32*)(g_yh + base);
#pragma unroll
    for (int t = 0; t < 12; t++) {
        float2 f0 = upk(acc2[2 * t + 0]);
        float2 f1 = upk(acc2[2 * t + 1]);
        yh[2 * t + 0] = cvt2h(f0.x, f0.y);
        yh[2 * t + 1] = cvt2h(f1.x, f1.y);
    }
}

// ---------------------------------------------------------------------------
extern "C" void kernel_launch(void* const* d_in, const int* in_sizes, int n_in,
                              void* d_out, int out_size)
{
    const float* x      = (const float*)d_in[0];
    const float* w_qkv  = (const float*)d_in[1];
    const float* w_proj = (const float*)d_in[2];
    const float* b_proj = (const float*)d_in[3];
    float* out = (float*)d_out;

    const int n4x = M_ * C_ / 4;
    const int n4q = QKVC * C_ / 4;
    const int n4p = C_ * C_ / 4;
    k_split<0><<<(n4x + 255) / 256, 256>>>(x, n4x);
    k_split<1><<<(n4q + 255) / 256, 256>>>(w_qkv, n4q);
    k_split<2><<<(n4p + 255) / 256, 256>>>(w_proj, n4p);

    dim3 g1(QKVC / 128, M_ / 128);        // 9 x 512
    k_gemm<0><<<g1, 256, GEMM_SMEM>>>(nullptr, nullptr);

    k_nred<<<6144, 32>>>();

    dim3 g2(8, 64);
    k_logits<<<g2, 256>>>();

    k_softmax<<<64, 48>>>();

    dim3 g3(32, 64);
    k_av<<<g3, 256>>>();

    dim3 g4(C_ / 128, M_ / 128);          // 3 x 512
    k_gemm<1><<<g4, 256, GEMM_SMEM>>>(b_proj, out);
}

// round 11
// speedup vs baseline: 1.4624x; 1.1603x over previous
#include <cuda_runtime.h>
#include <cuda_fp16.h>
#include <math.h>
#include <stdint.h>

#define B_   8
#define N_   8192
#define C_   384
#define M_   65536
#define QKVC 1152

typedef unsigned long long u64;
typedef unsigned int u32;

// Scratch (static device arrays)
__device__ __half g_qkvTh[9216L * N_];        // fp16 [which(3)][b][h][d][n]
__device__ float g_rn[6144];
__device__ float g_nsq[6144L * 128];          // norm^2 partials [row][ntile64]
__device__ float g_Spart[8 * 64 * 2304];
__device__ float g_attnT[64 * 2304];
__device__ __half g_xh[(size_t)M_ * C_];      // A of GEMM1: fp16(x)
__device__ __half g_yh[(size_t)M_ * C_];      // A of GEMM2: fp16(y)
__device__ __half g_wqh[QKVC * C_];           // fp16(w_qkv)
__device__ __half g_wph[C_ * C_];             // fp16(w_proj)

// ---- helpers ----------------------------------------------------------------
__device__ __forceinline__ u64 pk2(float a, float b) {
    u64 r; asm("mov.b64 %0, {%1,%2};" : "=l"(r) : "f"(a), "f"(b)); return r;
}
__device__ __forceinline__ float2 upk(u64 v) {
    float2 r; asm("mov.b64 {%0,%1}, %2;" : "=f"(r.x), "=f"(r.y) : "l"(v)); return r;
}
#define FMA2(acc, a, b) asm("fma.rn.f32x2 %0, %1, %2, %0;" : "+l"(acc) : "l"(a), "l"(b))

__device__ __forceinline__ u32 s2u(const void* p) {
    u32 a;
    asm("{ .reg .u64 t; cvta.to.shared.u64 t, %1; cvt.u32.u64 %0, t; }" : "=r"(a) : "l"(p));
    return a;
}
__device__ __forceinline__ void cp16(u32 dst, const void* src) {
    asm volatile("cp.async.cg.shared.global [%0], [%1], 16;" :: "r"(dst), "l"(src));
}
__device__ __forceinline__ void ldsm4(u32* r, u32 addr) {
    asm volatile("ldmatrix.sync.aligned.m8n8.x4.shared.b16 {%0,%1,%2,%3}, [%4];"
        : "=r"(r[0]), "=r"(r[1]), "=r"(r[2]), "=r"(r[3]) : "r"(addr));
}
__device__ __forceinline__ void mma_f16(float* d, const u32* a, u32 b0, u32 b1) {
    asm volatile("mma.sync.aligned.m16n8k16.row.col.f32.f16.f16.f32 "
        "{%0,%1,%2,%3}, {%4,%5,%6,%7}, {%8,%9}, {%0,%1,%2,%3};"
        : "+f"(d[0]), "+f"(d[1]), "+f"(d[2]), "+f"(d[3])
        : "r"(a[0]), "r"(a[1]), "r"(a[2]), "r"(a[3]), "r"(b0), "r"(b1));
}
__device__ __forceinline__ u32 packh2(__half a, __half b) {
    return (u32)*(unsigned short*)&a | ((u32)*(unsigned short*)&b << 16);
}
__device__ __forceinline__ u32 cvt2h(float a, float b) {
    return packh2(__float2half_rn(a), __float2half_rn(b));
}

// ---------------------------------------------------------------------------
// Pre-convert fp32 -> fp16   (SEL: 0=x, 1=w_qkv, 2=w_proj)
// ---------------------------------------------------------------------------
template<int SEL>
__global__ void k_split(const float* __restrict__ src, int n4)
{
    __half* dst = (SEL == 0) ? g_xh : (SEL == 1) ? g_wqh : g_wph;
    int i = blockIdx.x * 256 + threadIdx.x;
    if (i >= n4) return;
    float4 v = ((const float4*)src)[i];
    ((uint2*)dst)[i] = make_uint2(cvt2h(v.x, v.y), cvt2h(v.z, v.w));
}

// ---------------------------------------------------------------------------
// Tensor-core GEMM: C = A(m,k) * B(n,k)^T, K=384, plain fp16, fp32 accum
// 256 threads, 8 warps (2m x 4n), 64x32 warp tiles; 3-stage cp.async, BK=32
// (two 16-k subtiles per stage -> 12 outer iterations, 12 barriers).
// ---------------------------------------------------------------------------
#define STAGE_B   16384
#define GEMM_SMEM 49152   // 3 stages * 16KB; epilogue T uses 34816

template<int MODE>
__global__ void __launch_bounds__(256, 2)
k_gemm(const float* __restrict__ bias, float* __restrict__ outp)
{
    extern __shared__ char smem[];
    const u32 sb = s2u(smem);
    const int tid  = threadIdx.x;
    const int lane = tid & 31, wid = tid >> 5;
    const int wm = wid & 1, wn = wid >> 1;          // warp grid 2m x 4n
    const int row0 = blockIdx.y * 128;
    const int col0 = blockIdx.x * 128;

    const __half* Ah = (MODE == 0) ? g_xh  : g_yh;
    const __half* Bh = (MODE == 0) ? g_wqh : g_wph;

    float acc[4][4][4];
#pragma unroll
    for (int a = 0; a < 4; a++)
#pragma unroll
        for (int b = 0; b < 4; b++)
#pragma unroll
            for (int c = 0; c < 4; c++) acc[a][b][c] = 0.f;

    // cp.async: stage = [A0|A1|B0|B1], each 128 rows x 16 fp16 (32B/row, 4KB)
    const int crow = tid >> 1;
    const int cch  = tid & 1;
    const int cphys = cch ^ ((crow >> 2) & 1);
    const u32 cso = crow * 32 + cphys * 16;
    const size_t gra = (size_t)(row0 + crow) * C_ + cch * 8;
    const size_t grb = (size_t)(col0 + crow) * C_ + cch * 8;

    auto load_tile = [&](int it, int s) {
        const u32 st = sb + s * STAGE_B;
        const int k0 = it * 32;
        cp16(st +     0 + cso, Ah + gra + k0);
        cp16(st +  4096 + cso, Ah + gra + k0 + 16);
        cp16(st +  8192 + cso, Bh + grb + k0);
        cp16(st + 12288 + cso, Bh + grb + k0 + 16);
    };

    // ldmatrix.x4 address for 16-row group starting at r (row stride 32B)
    const int fr_off = (lane & 7) + ((lane >> 3) & 1) * 8;
    const int fr_ch  = lane >> 4;
    auto frag_addr = [&](u32 base, int r) -> u32 {
        int row = r + fr_off;
        int phys = fr_ch ^ ((row >> 2) & 1);
        return base + row * 32 + phys * 16;
    };

    auto compute = [&](int s, int half) {
        const u32 stA = sb + s * STAGE_B + half * 4096;
        const u32 stB = sb + s * STAGE_B + 8192 + half * 4096;
        u32 ah[4][4], bh[2][4];
#pragma unroll
        for (int mt = 0; mt < 4; mt++)
            ldsm4(ah[mt], frag_addr(stA, wm * 64 + mt * 16));
#pragma unroll
        for (int np = 0; np < 2; np++)
            ldsm4(bh[np], frag_addr(stB, wn * 32 + np * 16));
#pragma unroll
        for (int mt = 0; mt < 4; mt++)
#pragma unroll
            for (int np = 0; np < 2; np++)
#pragma unroll
                for (int sub = 0; sub < 2; sub++)
                    mma_f16(acc[mt][np * 2 + sub], ah[mt], bh[np][sub], bh[np][sub + 2]);
    };

    load_tile(0, 0);
    asm volatile("cp.async.commit_group;" ::: "memory");
    load_tile(1, 1);
    asm volatile("cp.async.commit_group;" ::: "memory");

#pragma unroll 1
    for (int it = 0; it < 12; it++) {
        if (it < 11) {
            asm volatile("cp.async.wait_group 1;" ::: "memory");
        } else {
            asm volatile("cp.async.wait_group 0;" ::: "memory");
        }
        __syncthreads();
        if (it + 2 < 12) {
            load_tile(it + 2, (it + 2) % 3);
            asm volatile("cp.async.commit_group;" ::: "memory");
        }
        compute(it % 3, 0);
        compute(it % 3, 1);
    }

    // Epilogue: stage halves through smem T[128][68] for coalesced stores
    float* T = (float*)smem;
    const int g = lane >> 2, tq = lane & 3;
    const int which = col0 / C_;

#pragma unroll 1
    for (int jh = 0; jh < 2; jh++) {
        __syncthreads();
        if (MODE == 0) {
            if (wm == jh) {
#pragma unroll
                for (int mt = 0; mt < 4; mt++)
#pragma unroll
                    for (int nt = 0; nt < 4; nt++) {
                        int ml = mt * 16 + g;
                        int nl = wn * 32 + nt * 8 + tq * 2;
#pragma unroll
                        for (int rr = 0; rr < 4; rr++)
                            T[(nl + (rr & 1)) * 68 + ml + (rr >> 1) * 8] = acc[mt][nt][rr];
                    }
            }
        } else {
            if ((wn >> 1) == jh) {
#pragma unroll
                for (int mt = 0; mt < 4; mt++)
#pragma unroll
                    for (int nt = 0; nt < 4; nt++) {
                        int ml = wm * 64 + mt * 16 + g;
                        int nl = (wn & 1) * 32 + nt * 8 + tq * 2;
#pragma unroll
                        for (int rr = 0; rr < 4; rr++)
                            T[(ml + (rr >> 1) * 8) * 68 + nl + (rr & 1)] = acc[mt][nt][rr];
                    }
            }
        }
        __syncthreads();
        if (MODE == 0) {
            const int bb = row0 >> 13;
            const int n0 = (row0 & (N_ - 1)) + jh * 64;
            const int ccb = col0 - which * C_;
            const int ntile = n0 >> 6;               // 0..127 (64-n granules)
#pragma unroll
            for (int t = 0; t < 8; t++) {
                int fid = tid + t * 256;
                int i = fid >> 4;                  // channel-local 0..127
                int j = (fid & 15) * 4;            // n offset 0..60
                float4 v = *(float4*)&T[i * 68 + j];
                __half hx = __float2half_rn(v.x), hy = __float2half_rn(v.y);
                __half hz = __float2half_rn(v.z), hw = __float2half_rn(v.w);
                int row = which * 3072 + bb * C_ + ccb + i;
                *(uint2*)(g_qkvTh + (size_t)row * N_ + n0 + j) =
                    make_uint2(packh2(hx, hy), packh2(hz, hw));
                if (which < 2) {
                    float rx = __half2float(hx), ry = __half2float(hy);
                    float rz = __half2float(hz), rw = __half2float(hw);
                    float sq = rx * rx + ry * ry + rz * rz + rw * rw;
                    sq += __shfl_xor_sync(0xffffffffu, sq, 1);
                    sq += __shfl_xor_sync(0xffffffffu, sq, 2);
                    sq += __shfl_xor_sync(0xffffffffu, sq, 4);
                    sq += __shfl_xor_sync(0xffffffffu, sq, 8);
                    if ((tid & 15) == 0)
                        g_nsq[(size_t)row * 128 + ntile] = sq;
                }
            }
        } else {
            const int c0 = col0 + jh * 64;
#pragma unroll
            for (int t = 0; t < 8; t++) {
                int fid = tid + t * 256;
                int i = fid >> 4;
                int j = (fid & 15) * 4;
                float4 v = *(float4*)&T[i * 68 + j];
                float4 bv = *(const float4*)(bias + c0 + j);
                v.x += bv.x; v.y += bv.y; v.z += bv.z; v.w += bv.w;
                *(float4*)(outp + (size_t)(row0 + i) * C_ + c0 + j) = v;
            }
        }
    }
}

// ---------------------------------------------------------------------------
// K2a: reduce norm^2 partials -> 1/max(norm,eps)
// ---------------------------------------------------------------------------
__global__ void k_nred()
{
    const int row = blockIdx.x;           // 0..6143
    const int t = threadIdx.x;            // 32 threads
    const float* p = g_nsq + (size_t)row * 128;
    float s = p[t] + p[t + 32] + p[t + 64] + p[t + 96];
#pragma unroll
    for (int o = 16; o > 0; o >>= 1)
        s += __shfl_xor_sync(0xffffffffu, s, o);
    if (t == 0)
        g_rn[row] = 1.0f / fmaxf(sqrtf(s), 1e-12f);
}

// ---------------------------------------------------------------------------
// K2b: Gram partials via mma.sync fp16 (exact same math as before: fp16
// operands, fp32 accumulate). CTA = (chunk, bh); 128 thr; warps 0-2 compute
// 16x48 each; 2-stage cp.async over 64-n slabs; 128B rows, XOR-8 swizzle.
// ---------------------------------------------------------------------------
__global__ void __launch_bounds__(128)
k_logits()
{
    const int chunk = blockIdx.x;     // 0..7 (1024 n)
    const int bh    = blockIdx.y;     // 0..63
    const int tid   = threadIdx.x;
    const int lane  = tid & 31, wid = tid >> 5;

    __shared__ __align__(16) char ls[2][12288];   // [stage][Q 6KB | K 6KB]
    const u32 sb = s2u(ls);

    auto load_stage = [&](int t, int s) {
#pragma unroll
        for (int i = 0; i < 6; i++) {
            int id  = tid + i * 128;          // 0..767
            int isK = id >= 384;
            int lid = id - isK * 384;
            int row = lid >> 3;               // 0..47
            int ch  = lid & 7;                // 16B chunk within 128B row
            size_t g = ((size_t)((isK ? 3072 : 0) + bh * 48 + row)) * N_
                     + (size_t)chunk * 1024 + t * 64 + ch * 8;
            cp16(sb + s * 12288 + isK * 6144 + row * 128 + ((ch ^ (row & 7)) * 16),
                 g_qkvTh + g);
        }
    };

    float acc[6][4];
#pragma unroll
    for (int j = 0; j < 6; j++)
#pragma unroll
        for (int r = 0; r < 4; r++) acc[j][r] = 0.f;

    const int fr_off = (lane & 7) + ((lane >> 3) & 1) * 8;
    const int fr_ch  = lane >> 4;
    auto faddr = [&](u32 base, int rbase, int kst) -> u32 {
        int row = rbase + fr_off;
        int ch  = (2 * kst + fr_ch) ^ (row & 7);
        return base + row * 128 + ch * 16;
    };

    auto compute = [&](int s) {
        if (wid >= 3) return;
        const u32 qb = sb + s * 12288;
        const u32 kb = qb + 6144;
#pragma unroll
        for (int kst = 0; kst < 4; kst++) {
            u32 aq[4];
            ldsm4(aq, faddr(qb, wid * 16, kst));
            u32 bk[3][4];
#pragma unroll
            for (int eg = 0; eg < 3; eg++)
                ldsm4(bk[eg], faddr(kb, eg * 16, kst));
#pragma unroll
            for (int eg = 0; eg < 3; eg++)
#pragma unroll
                for (int sub = 0; sub < 2; sub++)
                    mma_f16(acc[eg * 2 + sub], aq, bk[eg][sub], bk[eg][sub + 2]);
        }
    };

    load_stage(0, 0);
    asm volatile("cp.async.commit_group;" ::: "memory");

#pragma unroll 1
    for (int t = 0; t < 16; t++) {
        if (t + 1 < 16) {
            load_stage(t + 1, (t + 1) & 1);
            asm volatile("cp.async.commit_group;" ::: "memory");
            asm volatile("cp.async.wait_group 1;" ::: "memory");
        } else {
            asm volatile("cp.async.wait_group 0;" ::: "memory");
        }
        __syncthreads();
        compute(t & 1);
        __syncthreads();   // protect stage (t&1) before it's overwritten at t+2
    }

    if (wid < 3) {
        float* outp = g_Spart + ((size_t)chunk * 64 + bh) * 2304;
        const int g = lane >> 2, tq = lane & 3;
#pragma unroll
        for (int j = 0; j < 6; j++) {
            int e0 = j * 8 + tq * 2;
            int d0 = wid * 16 + g;
            *(float2*)&outp[d0 * 48 + e0]       = make_float2(acc[j][0], acc[j][1]);
            *(float2*)&outp[(d0 + 8) * 48 + e0] = make_float2(acc[j][2], acc[j][3]);
        }
    }
}

// ---------------------------------------------------------------------------
// K2c: softmax
// ---------------------------------------------------------------------------
__global__ void k_softmax()
{
    const int bh = blockIdx.x;
    const int d  = threadIdx.x;
    if (d >= 48) return;
    const float rq = g_rn[bh * 48 + d];
    const float* rk = g_rn + 3072 + bh * 48;

    float vals[48];
    float mx = -1e30f;
#pragma unroll
    for (int e = 0; e < 48; e++) {
        float s = 0.f;
#pragma unroll
        for (int c = 0; c < 8; c++)
            s += g_Spart[((size_t)c * 64 + bh) * 2304 + d * 48 + e];
        float v = s * rq * rk[e];
        vals[e] = v;
        mx = fmaxf(mx, v);
    }
    float sum = 0.f;
#pragma unroll
    for (int e = 0; e < 48; e++) {
        vals[e] = expf(vals[e] - mx);
        sum += vals[e];
    }
    float inv = 1.0f / sum;
#pragma unroll
    for (int e = 0; e < 48; e++)
        g_attnT[(size_t)bh * 2304 + e * 48 + d] = vals[e] * inv;
}

// ---------------------------------------------------------------------------
// K2d: y = attn @ v (v read fp16), emitted as fp16, row-major [m][j] for K3
// ---------------------------------------------------------------------------
__global__ void k_av()
{
    const int chunk = blockIdx.x;     // 0..31 (256 n each)
    const int bh    = blockIdx.y;
    const int tid   = threadIdx.x;
    __shared__ __align__(16) float At[2304];   // At[e*48 + d]
#pragma unroll
    for (int i = 0; i < 9; i++)
        At[tid + i * 256] = g_attnT[(size_t)bh * 2304 + tid + i * 256];
    __syncthreads();

    const int n = chunk * 256 + tid;
    const size_t vbase = ((size_t)(2 * 3072 + bh * 48)) * N_ + n;
    u64 acc2[24];
#pragma unroll
    for (int i = 0; i < 24; i++) acc2[i] = 0ULL;

#pragma unroll 4
    for (int e = 0; e < 48; e++) {
        float vv = __half2float(g_qkvTh[vbase + (size_t)e * N_]);
        u64 vp = pk2(vv, vv);
        const ulonglong2* arow = (const ulonglong2*)&At[e * 48];
#pragma unroll
        for (int t = 0; t < 12; t++) {
            ulonglong2 a2 = arow[t];
            FMA2(acc2[2 * t + 0], a2.x, vp);
            FMA2(acc2[2 * t + 1], a2.y, vp);
        }
    }
    const int b = bh >> 3, h = bh & 7;
    const size_t base = ((size_t)(b * N_ + n)) * C_ + h * 48;
    u32* yh = (u32*)(g_yh + base);
#pragma unroll
    for (int t = 0; t < 12; t++) {
        float2 f0 = upk(acc2[2 * t + 0]);
        float2 f1 = upk(acc2[2 * t + 1]);
        yh[2 * t + 0] = cvt2h(f0.x, f0.y);
        yh[2 * t + 1] = cvt2h(f1.x, f1.y);
    }
}

// ---------------------------------------------------------------------------
extern "C" void kernel_launch(void* const* d_in, const int* in_sizes, int n_in,
                              void* d_out, int out_size)
{
    const float* x      = (const float*)d_in[0];
    const float* w_qkv  = (const float*)d_in[1];
    const float* w_proj = (const float*)d_in[2];
    const float* b_proj = (const float*)d_in[3];
    float* out = (float*)d_out;

    const int n4x = M_ * C_ / 4;
    const int n4q = QKVC * C_ / 4;
    const int n4p = C_ * C_ / 4;
    k_split<0><<<(n4x + 255) / 256, 256>>>(x, n4x);
    k_split<1><<<(n4q + 255) / 256, 256>>>(w_qkv, n4q);
    k_split<2><<<(n4p + 255) / 256, 256>>>(w_proj, n4p);

    dim3 g1(QKVC / 128, M_ / 128);        // 9 x 512
    k_gemm<0><<<g1, 256, GEMM_SMEM>>>(nullptr, nullptr);

    k_nred<<<6144, 32>>>();

    dim3 g2(8, 64);
    k_logits<<<g2, 128>>>();

    k_softmax<<<64, 48>>>();

    dim3 g3(32, 64);
    k_av<<<g3, 256>>>();

    dim3 g4(C_ / 128, M_ / 128);          // 3 x 512
    k_gemm<1><<<g4, 256, GEMM_SMEM>>>(b_proj, out);
}

// round 15
// speedup vs baseline: 1.4784x; 1.0110x over previous
#include <cuda_runtime.h>
#include <cuda_fp16.h>
#include <math.h>
#include <stdint.h>

#define B_   8
#define N_   8192
#define C_   384
#define M_   65536
#define QKVC 1152

typedef unsigned long long u64;
typedef unsigned int u32;

// Scratch (static device arrays)
__device__ __half g_qkvTh[9216L * N_];        // fp16 [which(3)][b][h][d][n]
__device__ float g_rn[6144];
__device__ float g_nsq[6144L * 128];          // norm^2 partials [row][ntile64]
__device__ float g_Spart[8 * 64 * 2304];
__device__ float g_attnT[64 * 2304];          // fp32 attn TRANSPOSED [bh][e*48+d]
__device__ __half g_xh[(size_t)M_ * C_];      // A of GEMM1: fp16(x)
__device__ __half g_yh[(size_t)M_ * C_];      // y fp16 row-major [m][j]
__device__ __half g_wqh[QKVC * C_];           // fp16(w_qkv)
__device__ __half g_wph[C_ * C_];             // fp16(w_proj)

// ---- helpers ----------------------------------------------------------------
__device__ __forceinline__ u64 pk2(float a, float b) {
    u64 r; asm("mov.b64 %0, {%1,%2};" : "=l"(r) : "f"(a), "f"(b)); return r;
}
__device__ __forceinline__ float2 upk(u64 v) {
    float2 r; asm("mov.b64 {%0,%1}, %2;" : "=f"(r.x), "=f"(r.y) : "l"(v)); return r;
}
#define FMA2(acc, a, b) asm("fma.rn.f32x2 %0, %1, %2, %0;" : "+l"(acc) : "l"(a), "l"(b))

__device__ __forceinline__ u32 s2u(const void* p) {
    u32 a;
    asm("{ .reg .u64 t; cvta.to.shared.u64 t, %1; cvt.u32.u64 %0, t; }" : "=r"(a) : "l"(p));
    return a;
}
__device__ __forceinline__ void cp16(u32 dst, const void* src) {
    asm volatile("cp.async.cg.shared.global [%0], [%1], 16;" :: "r"(dst), "l"(src));
}
__device__ __forceinline__ void ldsm4(u32* r, u32 addr) {
    asm volatile("ldmatrix.sync.aligned.m8n8.x4.shared.b16 {%0,%1,%2,%3}, [%4];"
        : "=r"(r[0]), "=r"(r[1]), "=r"(r[2]), "=r"(r[3]) : "r"(addr));
}
__device__ __forceinline__ void mma_f16(float* d, const u32* a, u32 b0, u32 b1) {
    asm volatile("mma.sync.aligned.m16n8k16.row.col.f32.f16.f16.f32 "
        "{%0,%1,%2,%3}, {%4,%5,%6,%7}, {%8,%9}, {%0,%1,%2,%3};"
        : "+f"(d[0]), "+f"(d[1]), "+f"(d[2]), "+f"(d[3])
        : "r"(a[0]), "r"(a[1]), "r"(a[2]), "r"(a[3]), "r"(b0), "r"(b1));
}
__device__ __forceinline__ u32 packh2(__half a, __half b) {
    return (u32)*(unsigned short*)&a | ((u32)*(unsigned short*)&b << 16);
}
__device__ __forceinline__ u32 cvt2h(float a, float b) {
    return packh2(__float2half_rn(a), __float2half_rn(b));
}

// ---------------------------------------------------------------------------
// Pre-convert fp32 -> fp16   (SEL: 0=x, 1=w_qkv, 2=w_proj)
// ---------------------------------------------------------------------------
template<int SEL>
__global__ void k_split(const float* __restrict__ src, int n4)
{
    __half* dst = (SEL == 0) ? g_xh : (SEL == 1) ? g_wqh : g_wph;
    int i = blockIdx.x * 256 + threadIdx.x;
    if (i >= n4) return;
    float4 v = ((const float4*)src)[i];
    ((uint2*)dst)[i] = make_uint2(cvt2h(v.x, v.y), cvt2h(v.z, v.w));
}

// ---------------------------------------------------------------------------
// Tensor-core GEMM: C = A(m,k) * B(n,k)^T, K=384, plain fp16, fp32 accum
// 256 threads, 8 warps (2m x 4n), 64x32 warp tiles; 3-stage cp.async, BK=32.
// MODE 0: A = fp16(x) -> fp16 scatter into g_qkvTh + norm^2 partials
// MODE 1: A = fp16(y) row-major -> +bias, row-major fp32 out
// ---------------------------------------------------------------------------
#define STAGE_B   16384
#define GEMM_SMEM 49152

template<int MODE>
__global__ void __launch_bounds__(256, 2)
k_gemm(const float* __restrict__ bias, float* __restrict__ outp)
{
    extern __shared__ char smem[];
    const u32 sb = s2u(smem);
    const int tid  = threadIdx.x;
    const int lane = tid & 31, wid = tid >> 5;
    const int wm = wid & 1, wn = wid >> 1;          // warp grid 2m x 4n
    const int row0 = blockIdx.y * 128;
    const int col0 = blockIdx.x * 128;

    const __half* Ah = (MODE == 0) ? g_xh  : g_yh;
    const __half* Bh = (MODE == 0) ? g_wqh : g_wph;

    float acc[4][4][4];
#pragma unroll
    for (int a = 0; a < 4; a++)
#pragma unroll
        for (int b = 0; b < 4; b++)
#pragma unroll
            for (int c = 0; c < 4; c++) acc[a][b][c] = 0.f;

    const int crow = tid >> 1;
    const int cch  = tid & 1;
    const int cphys = cch ^ ((crow >> 2) & 1);
    const u32 cso = crow * 32 + cphys * 16;
    const size_t gra = (size_t)(row0 + crow) * C_ + cch * 8;
    const size_t grb = (size_t)(col0 + crow) * C_ + cch * 8;

    auto load_tile = [&](int it, int s) {
        const u32 st = sb + s * STAGE_B;
        const int k0 = it * 32;
        cp16(st +     0 + cso, Ah + gra + k0);
        cp16(st +  4096 + cso, Ah + gra + k0 + 16);
        cp16(st +  8192 + cso, Bh + grb + k0);
        cp16(st + 12288 + cso, Bh + grb + k0 + 16);
    };

    const int fr_off = (lane & 7) + ((lane >> 3) & 1) * 8;
    const int fr_ch  = lane >> 4;
    auto frag_addr = [&](u32 base, int r) -> u32 {
        int row = r + fr_off;
        int phys = fr_ch ^ ((row >> 2) & 1);
        return base + row * 32 + phys * 16;
    };

    auto compute = [&](int s, int half) {
        const u32 stA = sb + s * STAGE_B + half * 4096;
        const u32 stB = sb + s * STAGE_B + 8192 + half * 4096;
        u32 ah[4][4], bh[2][4];
#pragma unroll
        for (int mt = 0; mt < 4; mt++)
            ldsm4(ah[mt], frag_addr(stA, wm * 64 + mt * 16));
#pragma unroll
        for (int np = 0; np < 2; np++)
            ldsm4(bh[np], frag_addr(stB, wn * 32 + np * 16));
#pragma unroll
        for (int mt = 0; mt < 4; mt++)
#pragma unroll
            for (int np = 0; np < 2; np++)
#pragma unroll
                for (int sub = 0; sub < 2; sub++)
                    mma_f16(acc[mt][np * 2 + sub], ah[mt], bh[np][sub], bh[np][sub + 2]);
    };

    load_tile(0, 0);
    asm volatile("cp.async.commit_group;" ::: "memory");
    load_tile(1, 1);
    asm volatile("cp.async.commit_group;" ::: "memory");

#pragma unroll 1
    for (int it = 0; it < 12; it++) {
        if (it < 11) {
            asm volatile("cp.async.wait_group 1;" ::: "memory");
        } else {
            asm volatile("cp.async.wait_group 0;" ::: "memory");
        }
        __syncthreads();
        if (it + 2 < 12) {
            load_tile(it + 2, (it + 2) % 3);
            asm volatile("cp.async.commit_group;" ::: "memory");
        }
        compute(it % 3, 0);
        compute(it % 3, 1);
    }

    float* T = (float*)smem;
    const int g = lane >> 2, tq = lane & 3;
    const int which = col0 / C_;

#pragma unroll 1
    for (int jh = 0; jh < 2; jh++) {
        __syncthreads();
        if (MODE == 0) {
            if (wm == jh) {
#pragma unroll
                for (int mt = 0; mt < 4; mt++)
#pragma unroll
                    for (int nt = 0; nt < 4; nt++) {
                        int ml = mt * 16 + g;
                        int nl = wn * 32 + nt * 8 + tq * 2;
#pragma unroll
                        for (int rr = 0; rr < 4; rr++)
                            T[(nl + (rr & 1)) * 68 + ml + (rr >> 1) * 8] = acc[mt][nt][rr];
                    }
            }
        } else {
            if ((wn >> 1) == jh) {
#pragma unroll
                for (int mt = 0; mt < 4; mt++)
#pragma unroll
                    for (int nt = 0; nt < 4; nt++) {
                        int ml = wm * 64 + mt * 16 + g;
                        int nl = (wn & 1) * 32 + nt * 8 + tq * 2;
#pragma unroll
                        for (int rr = 0; rr < 4; rr++)
                            T[(ml + (rr >> 1) * 8) * 68 + nl + (rr & 1)] = acc[mt][nt][rr];
                    }
            }
        }
        __syncthreads();
        if (MODE == 0) {
            const int bb = row0 >> 13;
            const int n0 = (row0 & (N_ - 1)) + jh * 64;
            const int ccb = col0 - which * C_;
            const int ntile = n0 >> 6;
#pragma unroll
            for (int t = 0; t < 8; t++) {
                int fid = tid + t * 256;
                int i = fid >> 4;
                int j = (fid & 15) * 4;
                float4 v = *(float4*)&T[i * 68 + j];
                __half hx = __float2half_rn(v.x), hy = __float2half_rn(v.y);
                __half hz = __float2half_rn(v.z), hw = __float2half_rn(v.w);
                int row = which * 3072 + bb * C_ + ccb + i;
                *(uint2*)(g_qkvTh + (size_t)row * N_ + n0 + j) =
                    make_uint2(packh2(hx, hy), packh2(hz, hw));
                if (which < 2) {
                    float rx = __half2float(hx), ry = __half2float(hy);
                    float rz = __half2float(hz), rw = __half2float(hw);
                    float sq = rx * rx + ry * ry + rz * rz + rw * rw;
                    sq += __shfl_xor_sync(0xffffffffu, sq, 1);
                    sq += __shfl_xor_sync(0xffffffffu, sq, 2);
                    sq += __shfl_xor_sync(0xffffffffu, sq, 4);
                    sq += __shfl_xor_sync(0xffffffffu, sq, 8);
                    if ((tid & 15) == 0)
                        g_nsq[(size_t)row * 128 + ntile] = sq;
                }
            }
        } else {
            const int c0 = col0 + jh * 64;
#pragma unroll
            for (int t = 0; t < 8; t++) {
                int fid = tid + t * 256;
                int i = fid >> 4;
                int j = (fid & 15) * 4;
                float4 v = *(float4*)&T[i * 68 + j];
                float4 bv = *(const float4*)(bias + c0 + j);
                v.x += bv.x; v.y += bv.y; v.z += bv.z; v.w += bv.w;
                *(float4*)(outp + (size_t)(row0 + i) * C_ + c0 + j) = v;
            }
        }
    }
}

// ---------------------------------------------------------------------------
// K2a: reduce norm^2 partials -> 1/max(norm,eps)
// ---------------------------------------------------------------------------
__global__ void k_nred()
{
    const int row = blockIdx.x;
    const int t = threadIdx.x;
    const float* p = g_nsq + (size_t)row * 128;
    float s = p[t] + p[t + 32] + p[t + 64] + p[t + 96];
#pragma unroll
    for (int o = 16; o > 0; o >>= 1)
        s += __shfl_xor_sync(0xffffffffu, s, o);
    if (t == 0)
        g_rn[row] = 1.0f / fmaxf(sqrtf(s), 1e-12f);
}

// ---------------------------------------------------------------------------
// K2b: Gram partials via mma.sync fp16 (verbatim from passing R11)
// ---------------------------------------------------------------------------
__global__ void __launch_bounds__(128)
k_logits()
{
    const int chunk = blockIdx.x;
    const int bh    = blockIdx.y;
    const int tid   = threadIdx.x;
    const int lane  = tid & 31, wid = tid >> 5;

    __shared__ __align__(16) char ls[2][12288];
    const u32 sb = s2u(ls);

    auto load_stage = [&](int t, int s) {
#pragma unroll
        for (int i = 0; i < 6; i++) {
            int id  = tid + i * 128;
            int isK = id >= 384;
            int lid = id - isK * 384;
            int row = lid >> 3;
            int ch  = lid & 7;
            size_t g = ((size_t)((isK ? 3072 : 0) + bh * 48 + row)) * N_
                     + (size_t)chunk * 1024 + t * 64 + ch * 8;
            cp16(sb + s * 12288 + isK * 6144 + row * 128 + ((ch ^ (row & 7)) * 16),
                 g_qkvTh + g);
        }
    };

    float acc[6][4];
#pragma unroll
    for (int j = 0; j < 6; j++)
#pragma unroll
        for (int r = 0; r < 4; r++) acc[j][r] = 0.f;

    const int fr_off = (lane & 7) + ((lane >> 3) & 1) * 8;
    const int fr_ch  = lane >> 4;
    auto faddr = [&](u32 base, int rbase, int kst) -> u32 {
        int row = rbase + fr_off;
        int ch  = (2 * kst + fr_ch) ^ (row & 7);
        return base + row * 128 + ch * 16;
    };

    auto compute = [&](int s) {
        if (wid >= 3) return;
        const u32 qb = sb + s * 12288;
        const u32 kb = qb + 6144;
#pragma unroll
        for (int kst = 0; kst < 4; kst++) {
            u32 aq[4];
            ldsm4(aq, faddr(qb, wid * 16, kst));
            u32 bk[3][4];
#pragma unroll
            for (int eg = 0; eg < 3; eg++)
                ldsm4(bk[eg], faddr(kb, eg * 16, kst));
#pragma unroll
            for (int eg = 0; eg < 3; eg++)
#pragma unroll
                for (int sub = 0; sub < 2; sub++)
                    mma_f16(acc[eg * 2 + sub], aq, bk[eg][sub], bk[eg][sub + 2]);
        }
    };

    load_stage(0, 0);
    asm volatile("cp.async.commit_group;" ::: "memory");

#pragma unroll 1
    for (int t = 0; t < 16; t++) {
        if (t + 1 < 16) {
            load_stage(t + 1, (t + 1) & 1);
            asm volatile("cp.async.commit_group;" ::: "memory");
            asm volatile("cp.async.wait_group 1;" ::: "memory");
        } else {
            asm volatile("cp.async.wait_group 0;" ::: "memory");
        }
        __syncthreads();
        compute(t & 1);
        __syncthreads();
    }

    if (wid < 3) {
        float* outp = g_Spart + ((size_t)chunk * 64 + bh) * 2304;
        const int g = lane >> 2, tq = lane & 3;
#pragma unroll
        for (int j = 0; j < 6; j++) {
            int e0 = j * 8 + tq * 2;
            int d0 = wid * 16 + g;
            *(float2*)&outp[d0 * 48 + e0]       = make_float2(acc[j][0], acc[j][1]);
            *(float2*)&outp[(d0 + 8) * 48 + e0] = make_float2(acc[j][2], acc[j][3]);
        }
    }
}

// ---------------------------------------------------------------------------
// K2c: softmax -> fp32 attn TRANSPOSED [bh][e*48+d]  (verbatim R11)
// ---------------------------------------------------------------------------
__global__ void k_softmax()
{
    const int bh = blockIdx.x;
    const int d  = threadIdx.x;
    if (d >= 48) return;
    const float rq = g_rn[bh * 48 + d];
    const float* rk = g_rn + 3072 + bh * 48;

    float vals[48];
    float mx = -1e30f;
#pragma unroll
    for (int e = 0; e < 48; e++) {
        float s = 0.f;
#pragma unroll
        for (int c = 0; c < 8; c++)
            s += g_Spart[((size_t)c * 64 + bh) * 2304 + d * 48 + e];
        float v = s * rq * rk[e];
        vals[e] = v;
        mx = fmaxf(mx, v);
    }
    float sum = 0.f;
#pragma unroll
    for (int e = 0; e < 48; e++) {
        vals[e] = expf(vals[e] - mx);
        sum += vals[e];
    }
    float inv = 1.0f / sum;
#pragma unroll
    for (int e = 0; e < 48; e++)
        g_attnT[(size_t)bh * 2304 + e * 48 + d] = vals[e] * inv;
}

// ---------------------------------------------------------------------------
// K2d: y = attn @ v (R11 proven FMA2 algorithm, 2 n-columns per thread)
// At[e*48+d] broadcast from smem; v read as __half2 pairs; two d-packed
// accumulator sets (one per n). y emitted fp16 row-major [m][h*48+d].
// ---------------------------------------------------------------------------
__global__ void __launch_bounds__(256)
k_av()
{
    const int chunk = blockIdx.x;     // 0..15 (512 n each)
    const int bh    = blockIdx.y;
    const int tid   = threadIdx.x;
    __shared__ __align__(16) float At[2304];   // At[e*48 + d]
#pragma unroll
    for (int i = 0; i < 9; i++)
        At[tid + i * 256] = g_attnT[(size_t)bh * 2304 + tid + i * 256];
    __syncthreads();

    const int n = chunk * 512 + tid * 2;
    const size_t vbase = ((size_t)(2 * 3072 + bh * 48)) * N_ + n;
    u64 acc0[24], acc1[24];
#pragma unroll
    for (int i = 0; i < 24; i++) { acc0[i] = 0ULL; acc1[i] = 0ULL; }

#pragma unroll 4
    for (int e = 0; e < 48; e++) {
        u32 vv = *(const u32*)(g_qkvTh + vbase + (size_t)e * N_);
        float2 vf = __half22float2(*(__half2*)&vv);
        u64 vp0 = pk2(vf.x, vf.x);
        u64 vp1 = pk2(vf.y, vf.y);
        const ulonglong2* arow = (const ulonglong2*)&At[e * 48];
#pragma unroll
        for (int t = 0; t < 12; t++) {
            ulonglong2 a2 = arow[t];
            FMA2(acc0[2 * t + 0], a2.x, vp0);
            FMA2(acc0[2 * t + 1], a2.y, vp0);
            FMA2(acc1[2 * t + 0], a2.x, vp1);
            FMA2(acc1[2 * t + 1], a2.y, vp1);
        }
    }
    const int b = bh >> 3, h = bh & 7;
    const size_t m0 = (size_t)b * N_ + n;
    u32* y0 = (u32*)(g_yh + m0 * C_ + h * 48);
    u32* y1 = (u32*)(g_yh + (m0 + 1) * C_ + h * 48);
#pragma unroll
    for (int t = 0; t < 12; t++) {
        float2 f0 = upk(acc0[2 * t + 0]);
        float2 f1 = upk(acc0[2 * t + 1]);
        y0[2 * t + 0] = cvt2h(f0.x, f0.y);
        y0[2 * t + 1] = cvt2h(f1.x, f1.y);
        float2 g0 = upk(acc1[2 * t + 0]);
        float2 g1 = upk(acc1[2 * t + 1]);
        y1[2 * t + 0] = cvt2h(g0.x, g0.y);
        y1[2 * t + 1] = cvt2h(g1.x, g1.y);
    }
}

// ---------------------------------------------------------------------------
extern "C" void kernel_launch(void* const* d_in, const int* in_sizes, int n_in,
                              void* d_out, int out_size)
{
    const float* x      = (const float*)d_in[0];
    const float* w_qkv  = (const float*)d_in[1];
    const float* w_proj = (const float*)d_in[2];
    const float* b_proj = (const float*)d_in[3];
    float* out = (float*)d_out;

    const int n4x = M_ * C_ / 4;
    const int n4q = QKVC * C_ / 4;
    const int n4p = C_ * C_ / 4;
    k_split<0><<<(n4x + 255) / 256, 256>>>(x, n4x);
    k_split<1><<<(n4q + 255) / 256, 256>>>(w_qkv, n4q);
    k_split<2><<<(n4p + 255) / 256, 256>>>(w_proj, n4p);

    dim3 g1(QKVC / 128, M_ / 128);        // 9 x 512
    k_gemm<0><<<g1, 256, GEMM_SMEM>>>(nullptr, nullptr);

    k_nred<<<6144, 32>>>();

    dim3 g2(8, 64);
    k_logits<<<g2, 128>>>();

    k_softmax<<<64, 48>>>();

    dim3 g3(16, 64);
    k_av<<<g3, 256>>>();

    dim3 g4(C_ / 128, M_ / 128);          // 3 x 512
    k_gemm<1><<<g4, 256, GEMM_SMEM>>>(b_proj, out);
}

// round 16
// speedup vs baseline: 1.5397x; 1.0414x over previous
#include <cuda_runtime.h>
#include <cuda_fp16.h>
#include <math.h>
#include <stdint.h>

#define B_   8
#define N_   8192
#define C_   384
#define M_   65536
#define QKVC 1152

typedef unsigned long long u64;
typedef unsigned int u32;

// Scratch (static device arrays)
__device__ __half g_qkvTh[9216L * N_];        // fp16 [which(3)][b][h][d][n]
__device__ float g_rn[6144];
__device__ float g_nsq[6144L * 64];           // norm^2 partials [row][ntile128]
__device__ float g_Spart[8 * 64 * 2304];
__device__ float g_attnT[64 * 2304];          // fp32 attn TRANSPOSED [bh][e*48+d]
__device__ __half g_xh[(size_t)M_ * C_];      // A of GEMM1: fp16(x)
__device__ __half g_yh[(size_t)M_ * C_];      // y fp16 row-major [m][j]
__device__ __half g_wqh[QKVC * C_];           // fp16(w_qkv)
__device__ __half g_wph[C_ * C_];             // fp16(w_proj)

// ---- helpers ----------------------------------------------------------------
__device__ __forceinline__ u64 pk2(float a, float b) {
    u64 r; asm("mov.b64 %0, {%1,%2};" : "=l"(r) : "f"(a), "f"(b)); return r;
}
__device__ __forceinline__ float2 upk(u64 v) {
    float2 r; asm("mov.b64 {%0,%1}, %2;" : "=f"(r.x), "=f"(r.y) : "l"(v)); return r;
}
#define FMA2(acc, a, b) asm("fma.rn.f32x2 %0, %1, %2, %0;" : "+l"(acc) : "l"(a), "l"(b))

__device__ __forceinline__ u32 s2u(const void* p) {
    u32 a;
    asm("{ .reg .u64 t; cvta.to.shared.u64 t, %1; cvt.u32.u64 %0, t; }" : "=r"(a) : "l"(p));
    return a;
}
__device__ __forceinline__ void cp16(u32 dst, const void* src) {
    asm volatile("cp.async.cg.shared.global [%0], [%1], 16;" :: "r"(dst), "l"(src));
}
__device__ __forceinline__ void ldsm4(u32* r, u32 addr) {
    asm volatile("ldmatrix.sync.aligned.m8n8.x4.shared.b16 {%0,%1,%2,%3}, [%4];"
        : "=r"(r[0]), "=r"(r[1]), "=r"(r[2]), "=r"(r[3]) : "r"(addr));
}
__device__ __forceinline__ void mma_f16(float* d, const u32* a, u32 b0, u32 b1) {
    asm volatile("mma.sync.aligned.m16n8k16.row.col.f32.f16.f16.f32 "
        "{%0,%1,%2,%3}, {%4,%5,%6,%7}, {%8,%9}, {%0,%1,%2,%3};"
        : "+f"(d[0]), "+f"(d[1]), "+f"(d[2]), "+f"(d[3])
        : "r"(a[0]), "r"(a[1]), "r"(a[2]), "r"(a[3]), "r"(b0), "r"(b1));
}
__device__ __forceinline__ u32 packh2(__half a, __half b) {
    return (u32)*(unsigned short*)&a | ((u32)*(unsigned short*)&b << 16);
}
__device__ __forceinline__ u32 cvt2h(float a, float b) {
    return packh2(__float2half_rn(a), __float2half_rn(b));
}

// ---------------------------------------------------------------------------
// Pre-convert fp32 -> fp16.  k_splitx: x.  k_splitw: w_qkv and w_proj fused.
// ---------------------------------------------------------------------------
__global__ void k_splitx(const float* __restrict__ src, int n4)
{
    int i = blockIdx.x * 256 + threadIdx.x;
    if (i >= n4) return;
    float4 v = ((const float4*)src)[i];
    ((uint2*)g_xh)[i] = make_uint2(cvt2h(v.x, v.y), cvt2h(v.z, v.w));
}

__global__ void k_splitw(const float* __restrict__ wq, const float* __restrict__ wp,
                         int n4q, int n4p)
{
    int i = blockIdx.x * 256 + threadIdx.x;
    if (i < n4q) {
        float4 v = ((const float4*)wq)[i];
        ((uint2*)g_wqh)[i] = make_uint2(cvt2h(v.x, v.y), cvt2h(v.z, v.w));
    } else if (i < n4q + n4p) {
        int j = i - n4q;
        float4 v = ((const float4*)wp)[j];
        ((uint2*)g_wph)[j] = make_uint2(cvt2h(v.x, v.y), cvt2h(v.z, v.w));
    }
}

// ---------------------------------------------------------------------------
// Tensor-core GEMM: C = A(m,k) * B(n,k)^T, K=384, plain fp16, fp32 accum
// 256 threads, 8 warps (2m x 4n), 64x32 warp tiles; 3-stage cp.async, BK=32.
// MODE 0: A = fp16(x) -> fp16 scatter into g_qkvTh + norm^2 partials
//         (single-pass fp16 epilogue staging)
// MODE 1: A = fp16(y) row-major -> +bias, row-major fp32 out (2-pass fp32)
// ---------------------------------------------------------------------------
#define STAGE_B   16384
#define GEMM_SMEM 49152

template<int MODE>
__global__ void __launch_bounds__(256, 2)
k_gemm(const float* __restrict__ bias, float* __restrict__ outp)
{
    extern __shared__ char smem[];
    const u32 sb = s2u(smem);
    const int tid  = threadIdx.x;
    const int lane = tid & 31, wid = tid >> 5;
    const int wm = wid & 1, wn = wid >> 1;          // warp grid 2m x 4n
    const int row0 = blockIdx.y * 128;
    const int col0 = blockIdx.x * 128;

    const __half* Ah = (MODE == 0) ? g_xh  : g_yh;
    const __half* Bh = (MODE == 0) ? g_wqh : g_wph;

    float acc[4][4][4];
#pragma unroll
    for (int a = 0; a < 4; a++)
#pragma unroll
        for (int b = 0; b < 4; b++)
#pragma unroll
            for (int c = 0; c < 4; c++) acc[a][b][c] = 0.f;

    const int crow = tid >> 1;
    const int cch  = tid & 1;
    const int cphys = cch ^ ((crow >> 2) & 1);
    const u32 cso = crow * 32 + cphys * 16;
    const size_t gra = (size_t)(row0 + crow) * C_ + cch * 8;
    const size_t grb = (size_t)(col0 + crow) * C_ + cch * 8;

    auto load_tile = [&](int it, int s) {
        const u32 st = sb + s * STAGE_B;
        const int k0 = it * 32;
        cp16(st +     0 + cso, Ah + gra + k0);
        cp16(st +  4096 + cso, Ah + gra + k0 + 16);
        cp16(st +  8192 + cso, Bh + grb + k0);
        cp16(st + 12288 + cso, Bh + grb + k0 + 16);
    };

    const int fr_off = (lane & 7) + ((lane >> 3) & 1) * 8;
    const int fr_ch  = lane >> 4;
    auto frag_addr = [&](u32 base, int r) -> u32 {
        int row = r + fr_off;
        int phys = fr_ch ^ ((row >> 2) & 1);
        return base + row * 32 + phys * 16;
    };

    auto compute = [&](int s, int half) {
        const u32 stA = sb + s * STAGE_B + half * 4096;
        const u32 stB = sb + s * STAGE_B + 8192 + half * 4096;
        u32 ah[4][4], bh[2][4];
#pragma unroll
        for (int mt = 0; mt < 4; mt++)
            ldsm4(ah[mt], frag_addr(stA, wm * 64 + mt * 16));
#pragma unroll
        for (int np = 0; np < 2; np++)
            ldsm4(bh[np], frag_addr(stB, wn * 32 + np * 16));
#pragma unroll
        for (int mt = 0; mt < 4; mt++)
#pragma unroll
            for (int np = 0; np < 2; np++)
#pragma unroll
                for (int sub = 0; sub < 2; sub++)
                    mma_f16(acc[mt][np * 2 + sub], ah[mt], bh[np][sub], bh[np][sub + 2]);
    };

    load_tile(0, 0);
    asm volatile("cp.async.commit_group;" ::: "memory");
    load_tile(1, 1);
    asm volatile("cp.async.commit_group;" ::: "memory");

#pragma unroll 1
    for (int it = 0; it < 12; it++) {
        if (it < 11) {
            asm volatile("cp.async.wait_group 1;" ::: "memory");
        } else {
            asm volatile("cp.async.wait_group 0;" ::: "memory");
        }
        __syncthreads();
        if (it + 2 < 12) {
            load_tile(it + 2, (it + 2) % 3);
            asm volatile("cp.async.commit_group;" ::: "memory");
        }
        compute(it % 3, 0);
        compute(it % 3, 1);
    }

    const int g = lane >> 2, tq = lane & 3;
    const int which = col0 / C_;

    if (MODE == 0) {
        // --- single-pass fp16 epilogue: T16[c 128][n 128], pitch 136 halves ---
        __half* T16 = (__half*)smem;
        __syncthreads();   // mainloop reads done before overwrite
#pragma unroll
        for (int mt = 0; mt < 4; mt++)
#pragma unroll
            for (int nt = 0; nt < 4; nt++) {
#pragma unroll
                for (int rr = 0; rr < 4; rr++) {
                    int c = wn * 32 + nt * 8 + tq * 2 + (rr & 1);
                    int n = wm * 64 + mt * 16 + g + (rr >> 1) * 8;
                    T16[c * 136 + n] = __float2half_rn(acc[mt][nt][rr]);
                }
            }
        __syncthreads();

        const int bb = row0 >> 13;
        const int n0 = row0 & (N_ - 1);
        const int ccb = col0 - which * C_;
        const int ntile = n0 >> 7;                 // 0..63 (128-n granules)
#pragma unroll
        for (int t = 0; t < 8; t++) {
            int fid = tid + t * 256;
            int i = fid >> 4;                      // channel-local 0..127
            int j = (fid & 15) * 8;                // n offset 0..120
            uint4 v = *(const uint4*)&T16[i * 136 + j];
            int row = which * 3072 + bb * C_ + ccb + i;
            *(uint4*)(g_qkvTh + (size_t)row * N_ + n0 + j) = v;
            if (which < 2) {
                const __half* hp = (const __half*)&v;
                float sq = 0.f;
#pragma unroll
                for (int q = 0; q < 8; q++) {
                    float f = __half2float(hp[q]);
                    sq += f * f;
                }
                sq += __shfl_xor_sync(0xffffffffu, sq, 1);
                sq += __shfl_xor_sync(0xffffffffu, sq, 2);
                sq += __shfl_xor_sync(0xffffffffu, sq, 4);
                sq += __shfl_xor_sync(0xffffffffu, sq, 8);
                if ((tid & 15) == 0)
                    g_nsq[(size_t)row * 64 + ntile] = sq;
            }
        }
    } else {
        // --- 2-pass fp32 epilogue (proven) ---
        float* T = (float*)smem;
#pragma unroll 1
        for (int jh = 0; jh < 2; jh++) {
            __syncthreads();
            if ((wn >> 1) == jh) {
#pragma unroll
                for (int mt = 0; mt < 4; mt++)
#pragma unroll
                    for (int nt = 0; nt < 4; nt++) {
                        int ml = wm * 64 + mt * 16 + g;
                        int nl = (wn & 1) * 32 + nt * 8 + tq * 2;
#pragma unroll
                        for (int rr = 0; rr < 4; rr++)
                            T[(ml + (rr >> 1) * 8) * 68 + nl + (rr & 1)] = acc[mt][nt][rr];
                    }
            }
            __syncthreads();
            const int c0 = col0 + jh * 64;
#pragma unroll
            for (int t = 0; t < 8; t++) {
                int fid = tid + t * 256;
                int i = fid >> 4;
                int j = (fid & 15) * 4;
                float4 v = *(float4*)&T[i * 68 + j];
                float4 bv = *(const float4*)(bias + c0 + j);
                v.x += bv.x; v.y += bv.y; v.z += bv.z; v.w += bv.w;
                *(float4*)(outp + (size_t)(row0 + i) * C_ + c0 + j) = v;
            }
        }
    }
}

// ---------------------------------------------------------------------------
// K2a: reduce norm^2 partials -> 1/max(norm,eps)
// ---------------------------------------------------------------------------
__global__ void k_nred()
{
    const int row = blockIdx.x;
    const int t = threadIdx.x;
    const float* p = g_nsq + (size_t)row * 64;
    float s = p[t] + p[t + 32];
#pragma unroll
    for (int o = 16; o > 0; o >>= 1)
        s += __shfl_xor_sync(0xffffffffu, s, o);
    if (t == 0)
        g_rn[row] = 1.0f / fmaxf(sqrtf(s), 1e-12f);
}

// ---------------------------------------------------------------------------
// K2b: Gram partials via mma.sync fp16 (verbatim proven)
// ---------------------------------------------------------------------------
__global__ void __launch_bounds__(128)
k_logits()
{
    const int chunk = blockIdx.x;
    const int bh    = blockIdx.y;
    const int tid   = threadIdx.x;
    const int lane  = tid & 31, wid = tid >> 5;

    __shared__ __align__(16) char ls[2][12288];
    const u32 sb = s2u(ls);

    auto load_stage = [&](int t, int s) {
#pragma unroll
        for (int i = 0; i < 6; i++) {
            int id  = tid + i * 128;
            int isK = id >= 384;
            int lid = id - isK * 384;
            int row = lid >> 3;
            int ch  = lid & 7;
            size_t g = ((size_t)((isK ? 3072 : 0) + bh * 48 + row)) * N_
                     + (size_t)chunk * 1024 + t * 64 + ch * 8;
            cp16(sb + s * 12288 + isK * 6144 + row * 128 + ((ch ^ (row & 7)) * 16),
                 g_qkvTh + g);
        }
    };

    float acc[6][4];
#pragma unroll
    for (int j = 0; j < 6; j++)
#pragma unroll
        for (int r = 0; r < 4; r++) acc[j][r] = 0.f;

    const int fr_off = (lane & 7) + ((lane >> 3) & 1) * 8;
    const int fr_ch  = lane >> 4;
    auto faddr = [&](u32 base, int rbase, int kst) -> u32 {
        int row = rbase + fr_off;
        int ch  = (2 * kst + fr_ch) ^ (row & 7);
        return base + row * 128 + ch * 16;
    };

    auto compute = [&](int s) {
        if (wid >= 3) return;
        const u32 qb = sb + s * 12288;
        const u32 kb = qb + 6144;
#pragma unroll
        for (int kst = 0; kst < 4; kst++) {
            u32 aq[4];
            ldsm4(aq, faddr(qb, wid * 16, kst));
            u32 bk[3][4];
#pragma unroll
            for (int eg = 0; eg < 3; eg++)
                ldsm4(bk[eg], faddr(kb, eg * 16, kst));
#pragma unroll
            for (int eg = 0; eg < 3; eg++)
#pragma unroll
                for (int sub = 0; sub < 2; sub++)
                    mma_f16(acc[eg * 2 + sub], aq, bk[eg][sub], bk[eg][sub + 2]);
        }
    };

    load_stage(0, 0);
    asm volatile("cp.async.commit_group;" ::: "memory");

#pragma unroll 1
    for (int t = 0; t < 16; t++) {
        if (t + 1 < 16) {
            load_stage(t + 1, (t + 1) & 1);
            asm volatile("cp.async.commit_group;" ::: "memory");
            asm volatile("cp.async.wait_group 1;" ::: "memory");
        } else {
            asm volatile("cp.async.wait_group 0;" ::: "memory");
        }
        __syncthreads();
        compute(t & 1);
        __syncthreads();
    }

    if (wid < 3) {
        float* outp = g_Spart + ((size_t)chunk * 64 + bh) * 2304;
        const int g = lane >> 2, tq = lane & 3;
#pragma unroll
        for (int j = 0; j < 6; j++) {
            int e0 = j * 8 + tq * 2;
            int d0 = wid * 16 + g;
            *(float2*)&outp[d0 * 48 + e0]       = make_float2(acc[j][0], acc[j][1]);
            *(float2*)&outp[(d0 + 8) * 48 + e0] = make_float2(acc[j][2], acc[j][3]);
        }
    }
}

// ---------------------------------------------------------------------------
// K2c: softmax -> fp32 attn TRANSPOSED [bh][e*48+d]
// ---------------------------------------------------------------------------
__global__ void k_softmax()
{
    const int bh = blockIdx.x;
    const int d  = threadIdx.x;
    if (d >= 48) return;
    const float rq = g_rn[bh * 48 + d];
    const float* rk = g_rn + 3072 + bh * 48;

    float vals[48];
    float mx = -1e30f;
#pragma unroll
    for (int e = 0; e < 48; e++) {
        float s = 0.f;
#pragma unroll
        for (int c = 0; c < 8; c++)
            s += g_Spart[((size_t)c * 64 + bh) * 2304 + d * 48 + e];
        float v = s * rq * rk[e];
        vals[e] = v;
        mx = fmaxf(mx, v);
    }
    float sum = 0.f;
#pragma unroll
    for (int e = 0; e < 48; e++) {
        vals[e] = expf(vals[e] - mx);
        sum += vals[e];
    }
    float inv = 1.0f / sum;
#pragma unroll
    for (int e = 0; e < 48; e++)
        g_attnT[(size_t)bh * 2304 + e * 48 + d] = vals[e] * inv;
}

// ---------------------------------------------------------------------------
// K2d: y = attn @ v (proven FMA2, 2 n-columns per thread)
// ---------------------------------------------------------------------------
__global__ void __launch_bounds__(256)
k_av()
{
    const int chunk = blockIdx.x;     // 0..15 (512 n each)
    const int bh    = blockIdx.y;
    const int tid   = threadIdx.x;
    __shared__ __align__(16) float At[2304];   // At[e*48 + d]
#pragma unroll
    for (int i = 0; i < 9; i++)
        At[tid + i * 256] = g_attnT[(size_t)bh * 2304 + tid + i * 256];
    __syncthreads();

    const int n = chunk * 512 + tid * 2;
    const size_t vbase = ((size_t)(2 * 3072 + bh * 48)) * N_ + n;
    u64 acc0[24], acc1[24];
#pragma unroll
    for (int i = 0; i < 24; i++) { acc0[i] = 0ULL; acc1[i] = 0ULL; }

#pragma unroll 4
    for (int e = 0; e < 48; e++) {
        u32 vv = *(const u32*)(g_qkvTh + vbase + (size_t)e * N_);
        float2 vf = __half22float2(*(__half2*)&vv);
        u64 vp0 = pk2(vf.x, vf.x);
        u64 vp1 = pk2(vf.y, vf.y);
        const ulonglong2* arow = (const ulonglong2*)&At[e * 48];
#pragma unroll
        for (int t = 0; t < 12; t++) {
            ulonglong2 a2 = arow[t];
            FMA2(acc0[2 * t + 0], a2.x, vp0);
            FMA2(acc0[2 * t + 1], a2.y, vp0);
            FMA2(acc1[2 * t + 0], a2.x, vp1);
            FMA2(acc1[2 * t + 1], a2.y, vp1);
        }
    }
    const int b = bh >> 3, h = bh & 7;
    const size_t m0 = (size_t)b * N_ + n;
    u32* y0 = (u32*)(g_yh + m0 * C_ + h * 48);
    u32* y1 = (u32*)(g_yh + (m0 + 1) * C_ + h * 48);
#pragma unroll
    for (int t = 0; t < 12; t++) {
        float2 f0 = upk(acc0[2 * t + 0]);
        float2 f1 = upk(acc0[2 * t + 1]);
        y0[2 * t + 0] = cvt2h(f0.x, f0.y);
        y0[2 * t + 1] = cvt2h(f1.x, f1.y);
        float2 g0 = upk(acc1[2 * t + 0]);
        float2 g1 = upk(acc1[2 * t + 1]);
        y1[2 * t + 0] = cvt2h(g0.x, g0.y);
        y1[2 * t + 1] = cvt2h(g1.x, g1.y);
    }
}

// ---------------------------------------------------------------------------
extern "C" void kernel_launch(void* const* d_in, const int* in_sizes, int n_in,
                              void* d_out, int out_size)
{
    const float* x      = (const float*)d_in[0];
    const float* w_qkv  = (const float*)d_in[1];
    const float* w_proj = (const float*)d_in[2];
    const float* b_proj = (const float*)d_in[3];
    float* out = (float*)d_out;

    const int n4x = M_ * C_ / 4;
    const int n4q = QKVC * C_ / 4;
    const int n4p = C_ * C_ / 4;
    k_splitx<<<(n4x + 255) / 256, 256>>>(x, n4x);
    k_splitw<<<(n4q + n4p + 255) / 256, 256>>>(w_qkv, w_proj, n4q, n4p);

    dim3 g1(QKVC / 128, M_ / 128);        // 9 x 512
    k_gemm<0><<<g1, 256, GEMM_SMEM>>>(nullptr, nullptr);

    k_nred<<<6144, 32>>>();

    dim3 g2(8, 64);
    k_logits<<<g2, 128>>>();

    k_softmax<<<64, 48>>>();

    dim3 g3(16, 64);
    k_av<<<g3, 256>>>();

    dim3 g4(C_ / 128, M_ / 128);          // 3 x 512
    k_gemm<1><<<g4, 256, GEMM_SMEM>>>(b_proj, out);
}

// round 17
// speedup vs baseline: 1.7104x; 1.1109x over previous
#include <cuda_runtime.h>
#include <cuda_fp16.h>
#include <math.h>
#include <stdint.h>

#define B_   8
#define N_   8192
#define C_   384
#define M_   65536
#define QKVC 1152

typedef unsigned long long u64;
typedef unsigned int u32;

// Scratch (static device arrays)
__device__ __half g_qkvTh[9216L * N_];        // fp16 [which(3)][b][h][d][n]
__device__ float g_rn[6144];                  // (unused placeholder, kept for layout)
__device__ float g_nsq[6144L * 64];           // norm^2 partials [row][ntile128]
__device__ float g_Spart[8 * 64 * 2304];
__device__ float g_attnT[64 * 2304];          // fp32 attn TRANSPOSED [bh][e*48+d]
__device__ __half g_xh[(size_t)M_ * C_];      // A of GEMM1: fp16(x)
__device__ __half g_yh[(size_t)M_ * C_];      // y fp16 row-major [m][j]
__device__ __half g_wqh[QKVC * C_];           // fp16(w_qkv)
__device__ __half g_wph[C_ * C_];             // fp16(w_proj)

// ---- helpers ----------------------------------------------------------------
__device__ __forceinline__ u64 pk2(float a, float b) {
    u64 r; asm("mov.b64 %0, {%1,%2};" : "=l"(r) : "f"(a), "f"(b)); return r;
}
__device__ __forceinline__ float2 upk(u64 v) {
    float2 r; asm("mov.b64 {%0,%1}, %2;" : "=f"(r.x), "=f"(r.y) : "l"(v)); return r;
}
#define FMA2(acc, a, b) asm("fma.rn.f32x2 %0, %1, %2, %0;" : "+l"(acc) : "l"(a), "l"(b))

__device__ __forceinline__ u32 s2u(const void* p) {
    u32 a;
    asm("{ .reg .u64 t; cvta.to.shared.u64 t, %1; cvt.u32.u64 %0, t; }" : "=r"(a) : "l"(p));
    return a;
}
__device__ __forceinline__ void cp16(u32 dst, const void* src) {
    asm volatile("cp.async.cg.shared.global [%0], [%1], 16;" :: "r"(dst), "l"(src));
}
__device__ __forceinline__ void ldsm4(u32* r, u32 addr) {
    asm volatile("ldmatrix.sync.aligned.m8n8.x4.shared.b16 {%0,%1,%2,%3}, [%4];"
        : "=r"(r[0]), "=r"(r[1]), "=r"(r[2]), "=r"(r[3]) : "r"(addr));
}
__device__ __forceinline__ void mma_f16(float* d, const u32* a, u32 b0, u32 b1) {
    asm volatile("mma.sync.aligned.m16n8k16.row.col.f32.f16.f16.f32 "
        "{%0,%1,%2,%3}, {%4,%5,%6,%7}, {%8,%9}, {%0,%1,%2,%3};"
        : "+f"(d[0]), "+f"(d[1]), "+f"(d[2]), "+f"(d[3])
        : "r"(a[0]), "r"(a[1]), "r"(a[2]), "r"(a[3]), "r"(b0), "r"(b1));
}
__device__ __forceinline__ u32 packh2(__half a, __half b) {
    return (u32)*(unsigned short*)&a | ((u32)*(unsigned short*)&b << 16);
}
__device__ __forceinline__ u32 cvt2h(float a, float b) {
    return packh2(__float2half_rn(a), __float2half_rn(b));
}

// ---------------------------------------------------------------------------
// Fused pre-convert fp32 -> fp16: x, w_qkv, w_proj in one launch
// ---------------------------------------------------------------------------
__global__ void k_splitall(const float* __restrict__ x,
                           const float* __restrict__ wq,
                           const float* __restrict__ wp,
                           int n4x, int n4q, int n4p)
{
    int i = blockIdx.x * 256 + threadIdx.x;
    if (i < n4x) {
        float4 v = ((const float4*)x)[i];
        ((uint2*)g_xh)[i] = make_uint2(cvt2h(v.x, v.y), cvt2h(v.z, v.w));
    } else if (i < n4x + n4q) {
        int j = i - n4x;
        float4 v = ((const float4*)wq)[j];
        ((uint2*)g_wqh)[j] = make_uint2(cvt2h(v.x, v.y), cvt2h(v.z, v.w));
    } else if (i < n4x + n4q + n4p) {
        int j = i - n4x - n4q;
        float4 v = ((const float4*)wp)[j];
        ((uint2*)g_wph)[j] = make_uint2(cvt2h(v.x, v.y), cvt2h(v.z, v.w));
    }
}

// ---------------------------------------------------------------------------
// Tensor-core GEMM: C = A(m,k) * B(n,k)^T, K=384, plain fp16, fp32 accum
// 256 threads, 8 warps (2m x 4n), 64x32 warp tiles; 3-stage cp.async, BK=32.
// MODE 0: A = fp16(x) -> fp16 scatter into g_qkvTh + norm^2 partials
// MODE 1: A = fp16(y) row-major -> +bias, row-major fp32 out
// ---------------------------------------------------------------------------
#define STAGE_B   16384
#define GEMM_SMEM 49152

template<int MODE>
__global__ void __launch_bounds__(256, 2)
k_gemm(const float* __restrict__ bias, float* __restrict__ outp)
{
    extern __shared__ char smem[];
    const u32 sb = s2u(smem);
    const int tid  = threadIdx.x;
    const int lane = tid & 31, wid = tid >> 5;
    const int wm = wid & 1, wn = wid >> 1;          // warp grid 2m x 4n
    const int row0 = blockIdx.y * 128;
    const int col0 = blockIdx.x * 128;

    const __half* Ah = (MODE == 0) ? g_xh  : g_yh;
    const __half* Bh = (MODE == 0) ? g_wqh : g_wph;

    float acc[4][4][4];
#pragma unroll
    for (int a = 0; a < 4; a++)
#pragma unroll
        for (int b = 0; b < 4; b++)
#pragma unroll
            for (int c = 0; c < 4; c++) acc[a][b][c] = 0.f;

    const int crow = tid >> 1;
    const int cch  = tid & 1;
    const int cphys = cch ^ ((crow >> 2) & 1);
    const u32 cso = crow * 32 + cphys * 16;
    const size_t gra = (size_t)(row0 + crow) * C_ + cch * 8;
    const size_t grb = (size_t)(col0 + crow) * C_ + cch * 8;

    auto load_tile = [&](int it, int s) {
        const u32 st = sb + s * STAGE_B;
        const int k0 = it * 32;
        cp16(st +     0 + cso, Ah + gra + k0);
        cp16(st +  4096 + cso, Ah + gra + k0 + 16);
        cp16(st +  8192 + cso, Bh + grb + k0);
        cp16(st + 12288 + cso, Bh + grb + k0 + 16);
    };

    const int fr_off = (lane & 7) + ((lane >> 3) & 1) * 8;
    const int fr_ch  = lane >> 4;
    auto frag_addr = [&](u32 base, int r) -> u32 {
        int row = r + fr_off;
        int phys = fr_ch ^ ((row >> 2) & 1);
        return base + row * 32 + phys * 16;
    };

    auto compute = [&](int s, int half) {
        const u32 stA = sb + s * STAGE_B + half * 4096;
        const u32 stB = sb + s * STAGE_B + 8192 + half * 4096;
        u32 ah[4][4], bh[2][4];
#pragma unroll
        for (int mt = 0; mt < 4; mt++)
            ldsm4(ah[mt], frag_addr(stA, wm * 64 + mt * 16));
#pragma unroll
        for (int np = 0; np < 2; np++)
            ldsm4(bh[np], frag_addr(stB, wn * 32 + np * 16));
#pragma unroll
        for (int mt = 0; mt < 4; mt++)
#pragma unroll
            for (int np = 0; np < 2; np++)
#pragma unroll
                for (int sub = 0; sub < 2; sub++)
                    mma_f16(acc[mt][np * 2 + sub], ah[mt], bh[np][sub], bh[np][sub + 2]);
    };

    load_tile(0, 0);
    asm volatile("cp.async.commit_group;" ::: "memory");
    load_tile(1, 1);
    asm volatile("cp.async.commit_group;" ::: "memory");

#pragma unroll 1
    for (int it = 0; it < 12; it++) {
        if (it < 11) {
            asm volatile("cp.async.wait_group 1;" ::: "memory");
        } else {
            asm volatile("cp.async.wait_group 0;" ::: "memory");
        }
        __syncthreads();
        if (it + 2 < 12) {
            load_tile(it + 2, (it + 2) % 3);
            asm volatile("cp.async.commit_group;" ::: "memory");
        }
        compute(it % 3, 0);
        compute(it % 3, 1);
    }

    const int g = lane >> 2, tq = lane & 3;
    const int which = col0 / C_;

    if (MODE == 0) {
        __half* T16 = (__half*)smem;
        __syncthreads();
#pragma unroll
        for (int mt = 0; mt < 4; mt++)
#pragma unroll
            for (int nt = 0; nt < 4; nt++) {
#pragma unroll
                for (int rr = 0; rr < 4; rr++) {
                    int c = wn * 32 + nt * 8 + tq * 2 + (rr & 1);
                    int n = wm * 64 + mt * 16 + g + (rr >> 1) * 8;
                    T16[c * 136 + n] = __float2half_rn(acc[mt][nt][rr]);
                }
            }
        __syncthreads();

        const int bb = row0 >> 13;
        const int n0 = row0 & (N_ - 1);
        const int ccb = col0 - which * C_;
        const int ntile = n0 >> 7;
#pragma unroll
        for (int t = 0; t < 8; t++) {
            int fid = tid + t * 256;
            int i = fid >> 4;
            int j = (fid & 15) * 8;
            uint4 v = *(const uint4*)&T16[i * 136 + j];
            int row = which * 3072 + bb * C_ + ccb + i;
            *(uint4*)(g_qkvTh + (size_t)row * N_ + n0 + j) = v;
            if (which < 2) {
                const __half* hp = (const __half*)&v;
                float sq = 0.f;
#pragma unroll
                for (int q = 0; q < 8; q++) {
                    float f = __half2float(hp[q]);
                    sq += f * f;
                }
                sq += __shfl_xor_sync(0xffffffffu, sq, 1);
                sq += __shfl_xor_sync(0xffffffffu, sq, 2);
                sq += __shfl_xor_sync(0xffffffffu, sq, 4);
                sq += __shfl_xor_sync(0xffffffffu, sq, 8);
                if ((tid & 15) == 0)
                    g_nsq[(size_t)row * 64 + ntile] = sq;
            }
        }
    } else {
        float* T = (float*)smem;
#pragma unroll 1
        for (int jh = 0; jh < 2; jh++) {
            __syncthreads();
            if ((wn >> 1) == jh) {
#pragma unroll
                for (int mt = 0; mt < 4; mt++)
#pragma unroll
                    for (int nt = 0; nt < 4; nt++) {
                        int ml = wm * 64 + mt * 16 + g;
                        int nl = (wn & 1) * 32 + nt * 8 + tq * 2;
#pragma unroll
                        for (int rr = 0; rr < 4; rr++)
                            T[(ml + (rr >> 1) * 8) * 68 + nl + (rr & 1)] = acc[mt][nt][rr];
                    }
            }
            __syncthreads();
            const int c0 = col0 + jh * 64;
#pragma unroll
            for (int t = 0; t < 8; t++) {
                int fid = tid + t * 256;
                int i = fid >> 4;
                int j = (fid & 15) * 4;
                float4 v = *(float4*)&T[i * 68 + j];
                float4 bv = *(const float4*)(bias + c0 + j);
                v.x += bv.x; v.y += bv.y; v.z += bv.z; v.w += bv.w;
                *(float4*)(outp + (size_t)(row0 + i) * C_ + c0 + j) = v;
            }
        }
    }
}

// ---------------------------------------------------------------------------
// K2b: Gram partials via mma.sync fp16 (verbatim proven)
// ---------------------------------------------------------------------------
__global__ void __launch_bounds__(128)
k_logits()
{
    const int chunk = blockIdx.x;
    const int bh    = blockIdx.y;
    const int tid   = threadIdx.x;
    const int lane  = tid & 31, wid = tid >> 5;

    __shared__ __align__(16) char ls[2][12288];
    const u32 sb = s2u(ls);

    auto load_stage = [&](int t, int s) {
#pragma unroll
        for (int i = 0; i < 6; i++) {
            int id  = tid + i * 128;
            int isK = id >= 384;
            int lid = id - isK * 384;
            int row = lid >> 3;
            int ch  = lid & 7;
            size_t g = ((size_t)((isK ? 3072 : 0) + bh * 48 + row)) * N_
                     + (size_t)chunk * 1024 + t * 64 + ch * 8;
            cp16(sb + s * 12288 + isK * 6144 + row * 128 + ((ch ^ (row & 7)) * 16),
                 g_qkvTh + g);
        }
    };

    float acc[6][4];
#pragma unroll
    for (int j = 0; j < 6; j++)
#pragma unroll
        for (int r = 0; r < 4; r++) acc[j][r] = 0.f;

    const int fr_off = (lane & 7) + ((lane >> 3) & 1) * 8;
    const int fr_ch  = lane >> 4;
    auto faddr = [&](u32 base, int rbase, int kst) -> u32 {
        int row = rbase + fr_off;
        int ch  = (2 * kst + fr_ch) ^ (row & 7);
        return base + row * 128 + ch * 16;
    };

    auto compute = [&](int s) {
        if (wid >= 3) return;
        const u32 qb = sb + s * 12288;
        const u32 kb = qb + 6144;
#pragma unroll
        for (int kst = 0; kst < 4; kst++) {
            u32 aq[4];
            ldsm4(aq, faddr(qb, wid * 16, kst));
            u32 bk[3][4];
#pragma unroll
            for (int eg = 0; eg < 3; eg++)
                ldsm4(bk[eg], faddr(kb, eg * 16, kst));
#pragma unroll
            for (int eg = 0; eg < 3; eg++)
#pragma unroll
                for (int sub = 0; sub < 2; sub++)
                    mma_f16(acc[eg * 2 + sub], aq, bk[eg][sub], bk[eg][sub + 2]);
        }
    };

    load_stage(0, 0);
    asm volatile("cp.async.commit_group;" ::: "memory");

#pragma unroll 1
    for (int t = 0; t < 16; t++) {
        if (t + 1 < 16) {
            load_stage(t + 1, (t + 1) & 1);
            asm volatile("cp.async.commit_group;" ::: "memory");
            asm volatile("cp.async.wait_group 1;" ::: "memory");
        } else {
            asm volatile("cp.async.wait_group 0;" ::: "memory");
        }
        __syncthreads();
        compute(t & 1);
        __syncthreads();
    }

    if (wid < 3) {
        float* outp = g_Spart + ((size_t)chunk * 64 + bh) * 2304;
        const int g = lane >> 2, tq = lane & 3;
#pragma unroll
        for (int j = 0; j < 6; j++) {
            int e0 = j * 8 + tq * 2;
            int d0 = wid * 16 + g;
            *(float2*)&outp[d0 * 48 + e0]       = make_float2(acc[j][0], acc[j][1]);
            *(float2*)&outp[(d0 + 8) * 48 + e0] = make_float2(acc[j][2], acc[j][3]);
        }
    }
}

// ---------------------------------------------------------------------------
// K2c: softmax (fused norm reduction + cooperative Spart load), 256 threads
// -> fp32 attn TRANSPOSED [bh][e*48+d]
// ---------------------------------------------------------------------------
__global__ void __launch_bounds__(256)
k_softmax()
{
    const int bh = blockIdx.x;
    const int tid = threadIdx.x;
    __shared__ float S[2304];
    __shared__ float RN[96];    // [0..47] = rq[d], [48..95] = rk[e]

    if (tid < 96) {
        int row = (tid < 48) ? (bh * 48 + tid) : (3072 + bh * 48 + (tid - 48));
        const float* p = g_nsq + (size_t)row * 64;
        float s = 0.f;
#pragma unroll
        for (int i = 0; i < 64; i++) s += p[i];
        RN[tid] = 1.0f / fmaxf(sqrtf(s), 1e-12f);
    }
#pragma unroll
    for (int j0 = 0; j0 < 9; j0++) {
        int j = tid + j0 * 256;
        float s = 0.f;
#pragma unroll
        for (int c = 0; c < 8; c++)
            s += g_Spart[((size_t)c * 64 + bh) * 2304 + j];
        S[j] = s;
    }
    __syncthreads();

    if (tid < 48) {
        const int d = tid;
        const float rq = RN[d];
        float vals[48];
        float mx = -1e30f;
#pragma unroll
        for (int e = 0; e < 48; e++) {
            float v = S[d * 48 + e] * rq * RN[48 + e];
            vals[e] = v;
            mx = fmaxf(mx, v);
        }
        float sum = 0.f;
#pragma unroll
        for (int e = 0; e < 48; e++) {
            vals[e] = expf(vals[e] - mx);
            sum += vals[e];
        }
        float inv = 1.0f / sum;
#pragma unroll
        for (int e = 0; e < 48; e++)
            g_attnT[(size_t)bh * 2304 + e * 48 + d] = vals[e] * inv;
    }
}

// ---------------------------------------------------------------------------
// K2d: y = attn @ v (proven FMA2, 2 n-columns per thread, uint4 y stores)
// ---------------------------------------------------------------------------
__global__ void __launch_bounds__(256)
k_av()
{
    const int chunk = blockIdx.x;     // 0..15 (512 n each)
    const int bh    = blockIdx.y;
    const int tid   = threadIdx.x;
    __shared__ __align__(16) float At[2304];   // At[e*48 + d]
#pragma unroll
    for (int i = 0; i < 9; i++)
        At[tid + i * 256] = g_attnT[(size_t)bh * 2304 + tid + i * 256];
    __syncthreads();

    const int n = chunk * 512 + tid * 2;
    const size_t vbase = ((size_t)(2 * 3072 + bh * 48)) * N_ + n;
    u64 acc0[24], acc1[24];
#pragma unroll
    for (int i = 0; i < 24; i++) { acc0[i] = 0ULL; acc1[i] = 0ULL; }

#pragma unroll 4
    for (int e = 0; e < 48; e++) {
        u32 vv = *(const u32*)(g_qkvTh + vbase + (size_t)e * N_);
        float2 vf = __half22float2(*(__half2*)&vv);
        u64 vp0 = pk2(vf.x, vf.x);
        u64 vp1 = pk2(vf.y, vf.y);
        const ulonglong2* arow = (const ulonglong2*)&At[e * 48];
#pragma unroll
        for (int t = 0; t < 12; t++) {
            ulonglong2 a2 = arow[t];
            FMA2(acc0[2 * t + 0], a2.x, vp0);
            FMA2(acc0[2 * t + 1], a2.y, vp0);
            FMA2(acc1[2 * t + 0], a2.x, vp1);
            FMA2(acc1[2 * t + 1], a2.y, vp1);
        }
    }
    const int b = bh >> 3, h = bh & 7;
    const size_t m0 = (size_t)b * N_ + n;
    u32 o0[24], o1[24];
#pragma unroll
    for (int t = 0; t < 12; t++) {
        float2 f0 = upk(acc0[2 * t + 0]);
        float2 f1 = upk(acc0[2 * t + 1]);
        o0[2 * t + 0] = cvt2h(f0.x, f0.y);
        o0[2 * t + 1] = cvt2h(f1.x, f1.y);
        float2 g0 = upk(acc1[2 * t + 0]);
        float2 g1 = upk(acc1[2 * t + 1]);
        o1[2 * t + 0] = cvt2h(g0.x, g0.y);
        o1[2 * t + 1] = cvt2h(g1.x, g1.y);
    }
    uint4* y0 = (uint4*)(g_yh + m0 * C_ + h * 48);
    uint4* y1 = (uint4*)(g_yh + (m0 + 1) * C_ + h * 48);
#pragma unroll
    for (int q = 0; q < 6; q++) {
        y0[q] = make_uint4(o0[4*q], o0[4*q+1], o0[4*q+2], o0[4*q+3]);
        y1[q] = make_uint4(o1[4*q], o1[4*q+1], o1[4*q+2], o1[4*q+3]);
    }
}

// ---------------------------------------------------------------------------
extern "C" void kernel_launch(void* const* d_in, const int* in_sizes, int n_in,
                              void* d_out, int out_size)
{
    const float* x      = (const float*)d_in[0];
    const float* w_qkv  = (const float*)d_in[1];
    const float* w_proj = (const float*)d_in[2];
    const float* b_proj = (const float*)d_in[3];
    float* out = (float*)d_out;

    const int n4x = M_ * C_ / 4;
    const int n4q = QKVC * C_ / 4;
    const int n4p = C_ * C_ / 4;
    k_splitall<<<(n4x + n4q + n4p + 255) / 256, 256>>>(x, w_qkv, w_proj, n4x, n4q, n4p);

    dim3 g1(QKVC / 128, M_ / 128);        // 9 x 512
    k_gemm<0><<<g1, 256, GEMM_SMEM>>>(nullptr, nullptr);

    dim3 g2(8, 64);
    k_logits<<<g2, 128>>>();

    k_softmax<<<64, 256>>>();

    dim3 g3(16, 64);
    k_av<<<g3, 256>>>();

    dim3 g4(C_ / 128, M_ / 128);          // 3 x 512
    k_gemm<1><<<g4, 256, GEMM_SMEM>>>(b_proj, out);
}